// round 2
// baseline (speedup 1.0000x reference)
#include <cuda_runtime.h>
#include <math.h>
#include <float.h>
#include <stdint.h>

#define NN 8192
#define DD 64
#define EE 524288

// ---------------- static device scratch (no allocations allowed) ------------
__device__ float g_AH [NN*DD];
__device__ float g_Z  [NN*DD];
__device__ float g_AZ1[NN*DD];
__device__ float g_AZ2[NN*DD];
__device__ float g_ft [NN*DD];
__device__ float g_w  [3][EE];
__device__ float g_e  [EE];
__device__ int   g_m  [NN];      // float-order-encoded max
__device__ float g_den[NN];
__device__ int   g_nm [NN];
__device__ float g_pool[3*DD];
__device__ float g_ncnt[3];
__device__ int   g_hist[NN];
__device__ int   g_off [NN+1];
__device__ int   g_cur [NN];
__device__ int   g_eid [EE];
__device__ int   g_sdst[EE];

// monotonic float<->int encoding for atomicMax on floats
__device__ __forceinline__ int fenc(float f){ int i=__float_as_int(f); return i>=0 ? i : (i ^ 0x7fffffff); }
__device__ __forceinline__ float fdec(int i){ return __int_as_float(i>=0 ? i : (i ^ 0x7fffffff)); }

// device-side selection of scratch matrices (NEVER pass __device__ arrays
// as kernel args from host — host shadow address is not the device address)
__device__ __forceinline__ const float* mat_src(int id){
    switch(id){ case 0: return g_AH; case 1: return g_Z; case 2: return g_AZ1; default: return g_AZ2; }
}
__device__ __forceinline__ float* mat_dst(int id){
    return id == 0 ? g_Z : g_ft;
}

// ---------------- init ------------------------------------------------------
__global__ void k_init_all(){
    int i = blockIdx.x*blockDim.x + threadIdx.x;
    int T = gridDim.x*blockDim.x;
    for (int j=i; j<NN; j+=T){ g_hist[j]=0; }
    if (i < 3*DD) g_pool[i] = 0.f;
    if (i == 0){ g_ncnt[0] = (float)NN; g_ncnt[1]=0.f; g_ncnt[2]=0.f; }
}

__global__ void k_motif_init(){
    int i = blockIdx.x*blockDim.x + threadIdx.x;
    if (i < NN){ g_m[i] = INT_MIN; g_den[i] = 0.f; g_nm[i] = 0; }
}

// ---------------- CSR-by-src build ------------------------------------------
__global__ void k_hist(const int* __restrict__ src){
    int e = blockIdx.x*blockDim.x + threadIdx.x;
    if (e < EE) atomicAdd(&g_hist[src[e]], 1);
}

__global__ void k_scan(){  // single block, 1024 threads, 8 elems/thread
    __shared__ int s[1024];
    int t = threadIdx.x;
    int base = t*8;
    int loc[8]; int sum = 0;
    #pragma unroll
    for (int i=0;i<8;i++){ loc[i]=sum; sum += g_hist[base+i]; }
    s[t] = sum;
    __syncthreads();
    for (int off=1; off<1024; off<<=1){
        int v = (t>=off) ? s[t-off] : 0;
        __syncthreads();
        s[t] += v;
        __syncthreads();
    }
    int ex = (t==0) ? 0 : s[t-1];
    #pragma unroll
    for (int i=0;i<8;i++){ int o = ex + loc[i]; g_off[base+i]=o; g_cur[base+i]=o; }
    if (t == 1023) g_off[NN] = ex + sum;
}

__global__ void k_scatter(const int* __restrict__ src, const int* __restrict__ dst){
    int e = blockIdx.x*blockDim.x + threadIdx.x;
    if (e >= EE) return;
    int p = atomicAdd(&g_cur[src[e]], 1);
    g_eid[p]  = e;
    g_sdst[p] = dst[e];
}

// ---------------- dedup weights: w0[e] = 1/multiplicity --------------------
__global__ void k_weights(){
    __shared__ int sd[8*512];
    int wl   = threadIdx.x >> 5;
    int row  = blockIdx.x*8 + wl;
    if (row >= NN) return;
    int lane = threadIdx.x & 31;
    int lo = g_off[row], hi = g_off[row+1];
    int L = hi - lo;
    int* my = sd + wl*512;
    if (L <= 512){
        for (int i=lane; i<L; i+=32) my[i] = g_sdst[lo+i];
        __syncwarp();
        for (int i=lane; i<L; i+=32){
            int dv = my[i]; int c = 0;
            for (int j=0;j<L;j++) c += (my[j]==dv);
            g_w[0][g_eid[lo+i]] = 1.f/(float)c;
        }
    } else {  // pathological fallback
        for (int i=lane; i<L; i+=32){
            int dv = g_sdst[lo+i]; int c = 0;
            for (int j=0;j<L;j++) c += (g_sdst[lo+j]==dv);
            g_w[0][g_eid[lo+i]] = 1.f/(float)c;
        }
    }
}

// w1/w2: gated by dense A1/A2 at edge positions
__global__ void k_masks(const int* __restrict__ src, const int* __restrict__ dst,
                        const float* __restrict__ A1, const float* __restrict__ A2){
    int e = blockIdx.x*blockDim.x + threadIdx.x;
    if (e >= EE) return;
    size_t idx = (size_t)src[e]*NN + dst[e];
    float w0 = g_w[0][e];
    g_w[1][e] = (A1[idx] > 0.f) ? w0 : 0.f;
    g_w[2][e] = (A2[idx] > 0.f) ? w0 : 0.f;
}

// ---------------- sparse row aggregations ----------------------------------
// AH[u] = sum_e w0 * h[dst_e]   (warp per row; lane covers 2 feature dims)
__global__ void k_aggH(const float* __restrict__ h){
    int warp = (blockIdx.x*blockDim.x + threadIdx.x) >> 5;
    if (warp >= NN) return;
    int lane = threadIdx.x & 31;
    int lo = g_off[warp], hi = g_off[warp+1];
    float ax=0.f, ay=0.f;
    for (int i=lo; i<hi; i++){
        int eid = g_eid[i];
        float w = g_w[0][eid];
        float2 v = ((const float2*)(h + (size_t)g_sdst[i]*DD))[lane];
        ax += w*v.x; ay += w*v.y;
    }
    ((float2*)(g_AH + (size_t)warp*DD))[lane] = make_float2(ax, ay);
}

// AZ1[u], AZ2[u] fused (single gather of Z[dst])
__global__ void k_aggZ(){
    int warp = (blockIdx.x*blockDim.x + threadIdx.x) >> 5;
    if (warp >= NN) return;
    int lane = threadIdx.x & 31;
    int lo = g_off[warp], hi = g_off[warp+1];
    float a1x=0.f,a1y=0.f,a2x=0.f,a2y=0.f;
    for (int i=lo; i<hi; i++){
        int eid = g_eid[i];
        float w1 = g_w[1][eid];
        float w2 = g_w[2][eid];
        float2 v = ((const float2*)(g_Z + (size_t)g_sdst[i]*DD))[lane];
        a1x += w1*v.x; a1y += w1*v.y;
        a2x += w2*v.x; a2y += w2*v.y;
    }
    ((float2*)(g_AZ1 + (size_t)warp*DD))[lane] = make_float2(a1x, a1y);
    ((float2*)(g_AZ2 + (size_t)warp*DD))[lane] = make_float2(a2x, a2y);
}

// ---------------- small GEMM: C[N,64] = SRC[N,64] @ B (opt transpose, bias) --
// SRC/DST chosen by id INSIDE device code (see mat_src/mat_dst note above).
template<bool BT, bool BIAS>
__global__ void k_gemm(int srcId, const float* __restrict__ B,
                       const float* __restrict__ bias, int dstId){
    const float* __restrict__ Am = mat_src(srcId);
    float* __restrict__ Cm = mat_dst(dstId);
    __shared__ float Bs[DD*DD];
    __shared__ float As[64*DD];
    int t = threadIdx.x;  // 256
    for (int x=t; x<DD*DD; x+=256){
        int j = x / DD, i = x % DD;
        Bs[x] = BT ? B[i*DD + j] : B[j*DD + i];
    }
    int r0 = blockIdx.x * 64;
    for (int x=t; x<64*DD; x+=256) As[x] = Am[(size_t)r0*DD + x];
    __syncthreads();
    int rl = t >> 2;          // 0..63 local row
    int cg = (t & 3) * 16;    // col group
    float acc[16];
    #pragma unroll
    for (int i=0;i<16;i++) acc[i] = BIAS ? bias[cg+i] : 0.f;
    for (int j=0;j<DD;j++){
        float a = As[rl*DD + j];
        #pragma unroll
        for (int i=0;i<16;i++) acc[i] += a * Bs[j*DD + cg + i];
    }
    #pragma unroll
    for (int i=0;i<16;i++) Cm[(size_t)(r0+rl)*DD + cg + i] = acc[i];
}

// ---------------- attention passes ------------------------------------------
// pass 1: e = <ft[src], ft[dst]>/8 ; atomicMax into m[dst]  (warp per edge)
__global__ void k_epass(const int* __restrict__ src, const int* __restrict__ dst, int k){
    int e = (blockIdx.x*blockDim.x + threadIdx.x) >> 5;
    if (e >= EE) return;
    float wv = g_w[k][e];
    if (wv <= 0.f) return;            // warp-uniform
    int s = src[e], d = dst[e];
    int lane = threadIdx.x & 31;
    float2 a = ((const float2*)(g_ft + (size_t)s*DD))[lane];
    float2 b = ((const float2*)(g_ft + (size_t)d*DD))[lane];
    float p = a.x*b.x + a.y*b.y;
    #pragma unroll
    for (int o=16;o;o>>=1) p += __shfl_xor_sync(0xffffffffu, p, o);
    p *= 0.125f;                       // 1/sqrt(64)
    if (lane == 0){
        g_e[e] = p;
        atomicMax(&g_m[d], fenc(p));
    }
}

// pass 2: ex = exp(e - m[dst]); den[dst] += ex; mark nmask (thread per edge)
__global__ void k_expass(const int* __restrict__ src, const int* __restrict__ dst, int k){
    int e = blockIdx.x*blockDim.x + threadIdx.x;
    if (e >= EE) return;
    if (g_w[k][e] <= 0.f) return;
    int d = dst[e];
    float m = fdec(g_m[d]);
    float ex = expf(g_e[e] - m);
    g_e[e] = ex;
    atomicAdd(&g_den[d], ex);
    if (k){ g_nm[src[e]] = 1; g_nm[d] = 1; }
}

// pass 3: pool[k] += alpha * ft[src]  (warp per edge, block-level partials)
__global__ void k_aggpass(const int* __restrict__ src, const int* __restrict__ dst, int k){
    __shared__ float sacc[DD];
    int t = threadIdx.x;
    if (t < DD) sacc[t] = 0.f;
    __syncthreads();
    int lane = t & 31;
    int gw = (blockIdx.x*blockDim.x + t) >> 5;
    int nw = (gridDim.x*blockDim.x) >> 5;
    float ax=0.f, ay=0.f;
    for (int e=gw; e<EE; e+=nw){
        float wv = g_w[k][e];
        if (wv <= 0.f) continue;
        float den = g_den[dst[e]];
        float alpha = g_e[e] / fmaxf(den, 1e-9f);
        float2 a = ((const float2*)(g_ft + (size_t)src[e]*DD))[lane];
        ax += alpha*a.x; ay += alpha*a.y;
    }
    atomicAdd(&sacc[2*lane],   ax);
    atomicAdd(&sacc[2*lane+1], ay);
    __syncthreads();
    if (t < DD) atomicAdd(&g_pool[k*DD + t], sacc[t]);
}

__global__ void k_ncount(int k){
    int i = blockIdx.x*blockDim.x + threadIdx.x;
    int v = (i < NN && g_nm[i]) ? 1 : 0;
    #pragma unroll
    for (int o=16;o;o>>=1) v += __shfl_xor_sync(0xffffffffu, v, o);
    if ((threadIdx.x & 31) == 0 && v) atomicAdd(&g_ncnt[k], (float)v);
}

// ---------------- final linear ----------------------------------------------
__global__ void k_final(const float* __restrict__ lw, const float* __restrict__ lb,
                        float* __restrict__ out){
    __shared__ float s0[3*DD], s1[3*DD];
    int j = threadIdx.x;   // 192
    int k = j >> 6;
    float cnt = fmaxf(g_ncnt[k], 1.f);
    float p = g_pool[j] / cnt;
    s0[j] = p * lw[j*2 + 0];
    s1[j] = p * lw[j*2 + 1];
    __syncthreads();
    if (j == 0){
        float a = 0.f, b = 0.f;
        for (int i=0;i<3*DD;i++){ a += s0[i]; b += s1[i]; }
        out[0] = a + lb[0];
        out[1] = b + lb[1];
    }
}

// ---------------- host launcher ----------------------------------------------
extern "C" void kernel_launch(void* const* d_in, const int* in_sizes, int n_in,
                              void* d_out, int out_size){
    const float* h    = (const float*)d_in[0];
    // d_in[1] (A) unused: every edge exists in A by construction
    const float* A1   = (const float*)d_in[2];
    const float* A2   = (const float*)d_in[3];
    const float* Ww   = (const float*)d_in[4];
    const float* Wb   = (const float*)d_in[5];
    const float* fc0  = (const float*)d_in[6];
    const float* fc1  = (const float*)d_in[7];
    const float* fc2  = (const float*)d_in[8];
    const float* linw = (const float*)d_in[9];
    const float* linb = (const float*)d_in[10];
    const int*   src  = (const int*)d_in[11];
    const int*   dst  = (const int*)d_in[12];
    float* out = (float*)d_out;

    const int TPB = 256;
    const int Eblocks = (EE + TPB - 1) / TPB;       // thread-per-edge grids
    const int EWblocks = EE / (TPB/32);              // warp-per-edge grids
    const int RWblocks = NN / (TPB/32);              // warp-per-row grids

    k_init_all<<<512, TPB>>>();
    k_hist<<<Eblocks, TPB>>>(src);
    k_scan<<<1, 1024>>>();
    k_scatter<<<Eblocks, TPB>>>(src, dst);
    k_weights<<<NN/8, TPB>>>();
    k_masks<<<Eblocks, TPB>>>(src, dst, A1, A2);
    k_aggH<<<RWblocks, TPB>>>(h);
    k_gemm<true, true><<<NN/64, 256>>>(0, Ww, Wb, 0);   // g_Z = g_AH @ Ww.T + Wb
    k_aggZ<<<RWblocks, TPB>>>();

    const float* fcs[3] = {fc0, fc1, fc2};
    for (int k = 0; k < 3; k++){
        int srcId = (k==0) ? 1 : (k==1 ? 2 : 3);         // g_Z / g_AZ1 / g_AZ2
        k_gemm<false, false><<<NN/64, 256>>>(srcId, fcs[k], nullptr, 1);  // -> g_ft
        k_motif_init<<<NN/TPB, TPB>>>();
        k_epass<<<EWblocks, TPB>>>(src, dst, k);
        k_expass<<<Eblocks, TPB>>>(src, dst, k);
        k_aggpass<<<1184, TPB>>>(src, dst, k);
        if (k) k_ncount<<<NN/TPB, TPB>>>(k);
    }
    k_final<<<1, 192>>>(linw, linb, out);
    (void)in_sizes; (void)n_in; (void)out_size;
}

// round 3
// speedup vs baseline: 1.6461x; 1.6461x over previous
#include <cuda_runtime.h>
#include <math.h>
#include <float.h>

#define NN 8192
#define DD 64
#define EE 524288

// ---------------- static device scratch -------------------------------------
__device__ float g_AH [NN*DD];
__device__ float g_Z  [NN*DD];
__device__ float g_AZ1[NN*DD];
__device__ float g_AZ2[NN*DD];
__device__ float g_ft0[NN*DD];
__device__ float g_ft1[NN*DD];
__device__ float g_ft2[NN*DD];
__device__ float g_w0 [EE];            // 1/multiplicity, src-CSR order
__device__ int   g_sent[EE];           // src-CSR entries: dst | m1<<14 | m2<<15
__device__ int   g_dent[EE];           // dst-CSR entries: src | m1<<14 | m2<<15
__device__ int   g_hists[NN], g_histd[NN];
__device__ int   g_offs[NN+1], g_offd[NN+1];
__device__ int   g_curs[NN],  g_curd[NN];
__device__ int   g_nm1[NN], g_nm2[NN];
__device__ float g_pool[3*DD];
__device__ float g_ncnt[3];

// device-side selection of scratch matrices (host-side &g_X is a host shadow
// address — never pass device globals as kernel args from host)
__device__ __forceinline__ const float* mat_src(int id){
    switch(id){ case 0: return g_AH; case 1: return g_Z; case 2: return g_AZ1; default: return g_AZ2; }
}
__device__ __forceinline__ float* mat_dst(int id){
    switch(id){ case 0: return g_Z; case 1: return g_ft0; case 2: return g_ft1; default: return g_ft2; }
}

// ---------------- init -------------------------------------------------------
__global__ void k_init(){
    int i = blockIdx.x*blockDim.x + threadIdx.x;
    int T = gridDim.x*blockDim.x;
    for (int j=i; j<NN; j+=T){ g_hists[j]=0; g_histd[j]=0; g_nm1[j]=0; g_nm2[j]=0; }
    if (i < 3*DD) g_pool[i] = 0.f;
    if (i == 0){ g_ncnt[0] = (float)NN; g_ncnt[1]=0.f; g_ncnt[2]=0.f; }
}

// ---------------- CSR builds (both directions) -------------------------------
__global__ void k_hist(const int* __restrict__ src, const int* __restrict__ dst){
    int e = blockIdx.x*blockDim.x + threadIdx.x;
    if (e < EE){ atomicAdd(&g_hists[src[e]], 1); atomicAdd(&g_histd[dst[e]], 1); }
}

__global__ void k_scan(){  // blockIdx 0 -> src CSR, 1 -> dst CSR
    int* hist = blockIdx.x ? g_histd : g_hists;
    int* off  = blockIdx.x ? g_offd  : g_offs;
    int* cur  = blockIdx.x ? g_curd  : g_curs;
    __shared__ int s[1024];
    int t = threadIdx.x;
    int base = t*8;
    int loc[8]; int sum = 0;
    #pragma unroll
    for (int i=0;i<8;i++){ loc[i]=sum; sum += hist[base+i]; }
    s[t] = sum;
    __syncthreads();
    for (int off2=1; off2<1024; off2<<=1){
        int v = (t>=off2) ? s[t-off2] : 0;
        __syncthreads();
        s[t] += v;
        __syncthreads();
    }
    int ex = (t==0) ? 0 : s[t-1];
    #pragma unroll
    for (int i=0;i<8;i++){ int o = ex + loc[i]; off[base+i]=o; cur[base+i]=o; }
    if (t == 1023) off[NN] = ex + sum;
}

// scatter + motif mask gather fused: one pass over edges
__global__ void k_scatter(const int* __restrict__ src, const int* __restrict__ dst,
                          const float* __restrict__ A1, const float* __restrict__ A2){
    int e = blockIdx.x*blockDim.x + threadIdx.x;
    if (e >= EE) return;
    int s = src[e], d = dst[e];
    size_t idx = (size_t)s*NN + d;
    int bits = ((A1[idx] > 0.f) ? (1<<14) : 0) | ((A2[idx] > 0.f) ? (1<<15) : 0);
    g_sent[atomicAdd(&g_curs[s], 1)] = d | bits;
    g_dent[atomicAdd(&g_curd[d], 1)] = s | bits;
}

// ---------------- dedup weights: w0 = 1/multiplicity (src-CSR order) ---------
__global__ void k_weights(){
    __shared__ int sd[8*512];
    int wl   = threadIdx.x >> 5;
    int row  = blockIdx.x*8 + wl;
    if (row >= NN) return;
    int lane = threadIdx.x & 31;
    int lo = g_offs[row], hi = g_offs[row+1];
    int L = hi - lo;
    int* my = sd + wl*512;
    if (L <= 512){
        for (int i=lane; i<L; i+=32) my[i] = g_sent[lo+i] & 0x3FFF;
        __syncwarp();
        for (int i=lane; i<L; i+=32){
            int dv = my[i]; int c = 0;
            for (int j=0;j<L;j++) c += (my[j]==dv);
            g_w0[lo+i] = 1.f/(float)c;
        }
    } else {
        for (int i=lane; i<L; i+=32){
            int dv = g_sent[lo+i] & 0x3FFF; int c = 0;
            for (int j=0;j<L;j++) c += ((g_sent[lo+j]&0x3FFF)==dv);
            g_w0[lo+i] = 1.f/(float)c;
        }
    }
}

// ---------------- sparse row aggregations ------------------------------------
__global__ void k_aggH(const float* __restrict__ h){
    int warp = (blockIdx.x*blockDim.x + threadIdx.x) >> 5;
    if (warp >= NN) return;
    int lane = threadIdx.x & 31;
    int lo = g_offs[warp], hi = g_offs[warp+1];
    float ax=0.f, ay=0.f;
    for (int i=lo; i<hi; i++){
        int w = g_sent[i];
        float w0 = g_w0[i];
        float2 v = ((const float2*)(h + (size_t)(w & 0x3FFF)*DD))[lane];
        ax += w0*v.x; ay += w0*v.y;
    }
    ((float2*)(g_AH + (size_t)warp*DD))[lane] = make_float2(ax, ay);
}

__global__ void k_aggZ(){
    int warp = (blockIdx.x*blockDim.x + threadIdx.x) >> 5;
    if (warp >= NN) return;
    int lane = threadIdx.x & 31;
    int lo = g_offs[warp], hi = g_offs[warp+1];
    float a1x=0.f,a1y=0.f,a2x=0.f,a2y=0.f;
    for (int i=lo; i<hi; i++){
        int w = g_sent[i];
        float w0 = g_w0[i];
        float w1 = (w & (1<<14)) ? w0 : 0.f;
        float w2 = (w & (1<<15)) ? w0 : 0.f;
        float2 v = ((const float2*)(g_Z + (size_t)(w & 0x3FFF)*DD))[lane];
        a1x += w1*v.x; a1y += w1*v.y;
        a2x += w2*v.x; a2y += w2*v.y;
    }
    ((float2*)(g_AZ1 + (size_t)warp*DD))[lane] = make_float2(a1x, a1y);
    ((float2*)(g_AZ2 + (size_t)warp*DD))[lane] = make_float2(a2x, a2y);
}

// ---------------- small GEMM: C[N,64] = SRC[N,64] @ B (opt transpose, bias) --
template<bool BT, bool BIAS>
__global__ void k_gemm(int srcId, const float* __restrict__ B,
                       const float* __restrict__ bias, int dstId){
    const float* __restrict__ Am = mat_src(srcId);
    float* __restrict__ Cm = mat_dst(dstId);
    __shared__ float Bs[DD*DD];
    __shared__ float As[64*DD];
    int t = threadIdx.x;  // 256
    for (int x=t; x<DD*DD; x+=256){
        int j = x / DD, i = x % DD;
        Bs[x] = BT ? B[i*DD + j] : B[j*DD + i];
    }
    int r0 = blockIdx.x * 64;
    for (int x=t; x<64*DD; x+=256) As[x] = Am[(size_t)r0*DD + x];
    __syncthreads();
    int rl = t >> 2;
    int cg = (t & 3) * 16;
    float acc[16];
    #pragma unroll
    for (int i=0;i<16;i++) acc[i] = BIAS ? bias[cg+i] : 0.f;
    for (int j=0;j<DD;j++){
        float a = As[rl*DD + j];
        #pragma unroll
        for (int i=0;i<16;i++) acc[i] += a * Bs[j*DD + cg + i];
    }
    #pragma unroll
    for (int i=0;i<16;i++) Cm[(size_t)(r0+rl)*DD + cg + i] = acc[i];
}

// ---------------- fused single-pass attention (all 3 motifs) -----------------
// warp per dst row; online softmax; per-edge ft[src] gathered exactly once.
#define ONLINE_UPD(m, den, ax, ay, p, vx, vy) do {       \
    float _mn = fmaxf((m), (p));                         \
    float _sc = __expf((m) - _mn);                       \
    float _w  = __expf((p) - _mn);                       \
    (den) = (den)*_sc + _w;                              \
    (ax)  = (ax)*_sc + _w*(vx);                          \
    (ay)  = (ay)*_sc + _w*(vy);                          \
    (m) = _mn;                                           \
} while(0)

__global__ void k_attn(){
    __shared__ float sacc[3*DD];
    int t = threadIdx.x;
    for (int j=t; j<3*DD; j+=256) sacc[j] = 0.f;
    __syncthreads();
    int lane = t & 31;
    int gw = (blockIdx.x*256 + t) >> 5;
    const int NW = 512*8;   // total warps in grid
    for (int d = gw; d < NN; d += NW){
        int lo = g_offd[d], hi = g_offd[d+1];
        if (lo == hi) continue;
        float2 f0 = ((const float2*)(g_ft0 + (size_t)d*DD))[lane];
        float2 f1 = ((const float2*)(g_ft1 + (size_t)d*DD))[lane];
        float2 f2 = ((const float2*)(g_ft2 + (size_t)d*DD))[lane];
        float m0=-FLT_MAX, den0=0.f, a0x=0.f, a0y=0.f;
        float m1=-FLT_MAX, den1=0.f, a1x=0.f, a1y=0.f;
        float m2=-FLT_MAX, den2=0.f, a2x=0.f, a2y=0.f;
        for (int i=lo; i<hi; i++){
            int w = g_dent[i];            // warp-uniform broadcast
            int s = w & 0x3FFF;
            float2 v0 = ((const float2*)(g_ft0 + (size_t)s*DD))[lane];
            float p0 = v0.x*f0.x + v0.y*f0.y;
            #pragma unroll
            for (int o=16;o;o>>=1) p0 += __shfl_xor_sync(0xffffffffu, p0, o);
            p0 *= 0.125f;
            ONLINE_UPD(m0, den0, a0x, a0y, p0, v0.x, v0.y);
            if (w & (1<<14)){
                float2 v1 = ((const float2*)(g_ft1 + (size_t)s*DD))[lane];
                float p1 = v1.x*f1.x + v1.y*f1.y;
                #pragma unroll
                for (int o=16;o;o>>=1) p1 += __shfl_xor_sync(0xffffffffu, p1, o);
                p1 *= 0.125f;
                ONLINE_UPD(m1, den1, a1x, a1y, p1, v1.x, v1.y);
                if (lane == 0){ g_nm1[s] = 1; g_nm1[d] = 1; }
            }
            if (w & (1<<15)){
                float2 v2 = ((const float2*)(g_ft2 + (size_t)s*DD))[lane];
                float p2 = v2.x*f2.x + v2.y*f2.y;
                #pragma unroll
                for (int o=16;o;o>>=1) p2 += __shfl_xor_sync(0xffffffffu, p2, o);
                p2 *= 0.125f;
                ONLINE_UPD(m2, den2, a2x, a2y, p2, v2.x, v2.y);
                if (lane == 0){ g_nm2[s] = 1; g_nm2[d] = 1; }
            }
        }
        // row results: agg[d] = acc/den; sum over rows (nmask folds in: den>0 iff masked-in)
        atomicAdd(&sacc[       2*lane  ], a0x/fmaxf(den0, 1e-9f));
        atomicAdd(&sacc[       2*lane+1], a0y/fmaxf(den0, 1e-9f));
        if (den1 > 0.f){
            atomicAdd(&sacc[DD   + 2*lane  ], a1x/den1);
            atomicAdd(&sacc[DD   + 2*lane+1], a1y/den1);
        }
        if (den2 > 0.f){
            atomicAdd(&sacc[2*DD + 2*lane  ], a2x/den2);
            atomicAdd(&sacc[2*DD + 2*lane+1], a2y/den2);
        }
    }
    __syncthreads();
    for (int j=t; j<3*DD; j+=256) atomicAdd(&g_pool[j], sacc[j]);
}

// ---------------- node counts for motif means ---------------------------------
__global__ void k_ncount(){
    int i = blockIdx.x*blockDim.x + threadIdx.x;
    int v1 = (i < NN && g_nm1[i]) ? 1 : 0;
    int v2 = (i < NN && g_nm2[i]) ? 1 : 0;
    #pragma unroll
    for (int o=16;o;o>>=1){
        v1 += __shfl_xor_sync(0xffffffffu, v1, o);
        v2 += __shfl_xor_sync(0xffffffffu, v2, o);
    }
    if ((threadIdx.x & 31) == 0){
        if (v1) atomicAdd(&g_ncnt[1], (float)v1);
        if (v2) atomicAdd(&g_ncnt[2], (float)v2);
    }
}

// ---------------- final linear -------------------------------------------------
__global__ void k_final(const float* __restrict__ lw, const float* __restrict__ lb,
                        float* __restrict__ out){
    __shared__ float s0[3*DD], s1[3*DD];
    int j = threadIdx.x;   // 192
    int k = j >> 6;
    float cnt = fmaxf(g_ncnt[k], 1.f);
    float p = g_pool[j] / cnt;
    s0[j] = p * lw[j*2 + 0];
    s1[j] = p * lw[j*2 + 1];
    __syncthreads();
    if (j == 0){
        float a = 0.f, b = 0.f;
        for (int i=0;i<3*DD;i++){ a += s0[i]; b += s1[i]; }
        out[0] = a + lb[0];
        out[1] = b + lb[1];
    }
}

// ---------------- host launcher -------------------------------------------------
extern "C" void kernel_launch(void* const* d_in, const int* in_sizes, int n_in,
                              void* d_out, int out_size){
    const float* h    = (const float*)d_in[0];
    // d_in[1] (A) unused: every edge exists in A by construction
    const float* A1   = (const float*)d_in[2];
    const float* A2   = (const float*)d_in[3];
    const float* Ww   = (const float*)d_in[4];
    const float* Wb   = (const float*)d_in[5];
    const float* fc0  = (const float*)d_in[6];
    const float* fc1  = (const float*)d_in[7];
    const float* fc2  = (const float*)d_in[8];
    const float* linw = (const float*)d_in[9];
    const float* linb = (const float*)d_in[10];
    const int*   src  = (const int*)d_in[11];
    const int*   dst  = (const int*)d_in[12];
    float* out = (float*)d_out;

    k_init   <<<64,   256>>>();
    k_hist   <<<2048, 256>>>(src, dst);
    k_scan   <<<2,   1024>>>();
    k_scatter<<<2048, 256>>>(src, dst, A1, A2);
    k_weights<<<1024, 256>>>();
    k_aggH   <<<1024, 256>>>(h);
    k_gemm<true,  true ><<<128, 256>>>(0, Ww,  Wb,      0);  // g_Z   = g_AH @ Ww.T + Wb
    k_aggZ   <<<1024, 256>>>();
    k_gemm<false, false><<<128, 256>>>(1, fc0, nullptr, 1);  // g_ft0 = g_Z   @ fc0
    k_gemm<false, false><<<128, 256>>>(2, fc1, nullptr, 2);  // g_ft1 = g_AZ1 @ fc1
    k_gemm<false, false><<<128, 256>>>(3, fc2, nullptr, 3);  // g_ft2 = g_AZ2 @ fc2
    k_attn   <<<512,  256>>>();
    k_ncount <<<32,   256>>>();
    k_final  <<<1,    192>>>(linw, linb, out);
    (void)in_sizes; (void)n_in; (void)out_size;
}

// round 4
// speedup vs baseline: 1.8315x; 1.1126x over previous
#include <cuda_runtime.h>
#include <math.h>
#include <float.h>

#define NN 8192
#define DD 64
#define EE 524288

// ---------------- static device scratch -------------------------------------
__device__ float g_AH [NN*DD];
__device__ float g_Z  [NN*DD];
__device__ float g_AZ1[NN*DD];
__device__ float g_AZ2[NN*DD];
__device__ float g_ft0[NN*DD];
__device__ float g_ft1[NN*DD];
__device__ float g_ft2[NN*DD];
__device__ float g_w0 [EE];            // 1/multiplicity, src-CSR order
__device__ int   g_sent[EE];           // src-CSR entries: dst | m1<<14 | m2<<15
__device__ int   g_dent[EE];           // dst-CSR entries: src | m1<<14 | m2<<15
__device__ int   g_hists[NN], g_histd[NN];
__device__ int   g_offs[NN+1], g_offd[NN+1];
__device__ int   g_curs[NN],  g_curd[NN];
__device__ int   g_nm1[NN], g_nm2[NN];
__device__ float g_pool[3*DD];

// device-side matrix selection (host &g_X is a host shadow address!)
__device__ __forceinline__ const float* mat_src(int id){
    switch(id){ case 0: return g_AH; case 1: return g_Z; case 2: return g_AZ1; default: return g_AZ2; }
}
__device__ __forceinline__ float* mat_dst(int id){
    switch(id){ case 0: return g_Z; case 1: return g_ft0; case 2: return g_ft1; default: return g_ft2; }
}

// ---------------- init -------------------------------------------------------
__global__ void k_init(){
    int i = blockIdx.x*blockDim.x + threadIdx.x;
    int T = gridDim.x*blockDim.x;
    for (int j=i; j<NN; j+=T){ g_hists[j]=0; g_histd[j]=0; g_nm1[j]=0; g_nm2[j]=0; }
    if (i < 3*DD) g_pool[i] = 0.f;
}

// ---------------- CSR builds (both directions) -------------------------------
__global__ void k_hist(const int* __restrict__ src, const int* __restrict__ dst){
    int e = blockIdx.x*blockDim.x + threadIdx.x;
    if (e < EE){ atomicAdd(&g_hists[src[e]], 1); atomicAdd(&g_histd[dst[e]], 1); }
}

__global__ void k_scan(){  // blockIdx 0 -> src CSR, 1 -> dst CSR
    int* hist = blockIdx.x ? g_histd : g_hists;
    int* off  = blockIdx.x ? g_offd  : g_offs;
    int* cur  = blockIdx.x ? g_curd  : g_curs;
    __shared__ int s[1024];
    int t = threadIdx.x;
    int base = t*8;
    int loc[8]; int sum = 0;
    #pragma unroll
    for (int i=0;i<8;i++){ loc[i]=sum; sum += hist[base+i]; }
    s[t] = sum;
    __syncthreads();
    for (int off2=1; off2<1024; off2<<=1){
        int v = (t>=off2) ? s[t-off2] : 0;
        __syncthreads();
        s[t] += v;
        __syncthreads();
    }
    int ex = (t==0) ? 0 : s[t-1];
    #pragma unroll
    for (int i=0;i<8;i++){ int o = ex + loc[i]; off[base+i]=o; cur[base+i]=o; }
    if (t == 1023) off[NN] = ex + sum;
}

// scatter + motif mask gather fused: one pass over edges
__global__ void k_scatter(const int* __restrict__ src, const int* __restrict__ dst,
                          const float* __restrict__ A1, const float* __restrict__ A2){
    int e = blockIdx.x*blockDim.x + threadIdx.x;
    if (e >= EE) return;
    int s = src[e], d = dst[e];
    size_t idx = (size_t)s*NN + d;
    float a1 = __ldcs(&A1[idx]);     // one-touch random: streaming, no L1 alloc
    float a2 = __ldcs(&A2[idx]);
    int bits = ((a1 > 0.f) ? (1<<14) : 0) | ((a2 > 0.f) ? (1<<15) : 0);
    g_sent[atomicAdd(&g_curs[s], 1)] = d | bits;
    g_dent[atomicAdd(&g_curd[d], 1)] = s | bits;
}

// ---------------- aggH fused with dedup-weight computation -------------------
// AH[u] = sum_e (1/mult) h[dst_e]; also emits g_w0 (src-CSR order) for aggZ.
__global__ void k_aggH(const float* __restrict__ h){
    __shared__ int   sd [8*512];
    __shared__ float swt[8*512];
    int wl   = threadIdx.x >> 5;
    int lane = threadIdx.x & 31;
    int row  = blockIdx.x*8 + wl;
    if (row >= NN) return;
    int lo = g_offs[row], hi = g_offs[row+1];
    int L = hi - lo;
    float ax=0.f, ay=0.f;
    if (L <= 512){
        int*   my = sd  + wl*512;
        float* mw = swt + wl*512;
        for (int i=lane; i<L; i+=32) my[i] = g_sent[lo+i];
        __syncwarp();
        for (int i=lane; i<L; i+=32){
            int dv = my[i] & 0x3FFF; int c = 0;
            for (int j=0;j<L;j++) c += ((my[j]&0x3FFF)==dv);
            float w = 1.f/(float)c;
            mw[i] = w;
            g_w0[lo+i] = w;
        }
        __syncwarp();
        for (int i=0; i<L; i++){
            float w0 = mw[i];
            float2 v = ((const float2*)(h + (size_t)(my[i] & 0x3FFF)*DD))[lane];
            ax += w0*v.x; ay += w0*v.y;
        }
    } else {  // pathological fallback
        for (int i=lane; i<L; i+=32){
            int dv = g_sent[lo+i] & 0x3FFF; int c = 0;
            for (int j=0;j<L;j++) c += ((g_sent[lo+j]&0x3FFF)==dv);
            g_w0[lo+i] = 1.f/(float)c;
        }
        __syncwarp();
        for (int i=lo; i<hi; i++){
            float w0 = g_w0[i];
            float2 v = ((const float2*)(h + (size_t)(g_sent[i] & 0x3FFF)*DD))[lane];
            ax += w0*v.x; ay += w0*v.y;
        }
    }
    ((float2*)(g_AH + (size_t)row*DD))[lane] = make_float2(ax, ay);
}

// AZ1[u], AZ2[u] fused (single gather of Z[dst])
__global__ void k_aggZ(){
    int warp = (blockIdx.x*blockDim.x + threadIdx.x) >> 5;
    if (warp >= NN) return;
    int lane = threadIdx.x & 31;
    int lo = g_offs[warp], hi = g_offs[warp+1];
    float a1x=0.f,a1y=0.f,a2x=0.f,a2y=0.f;
    for (int i=lo; i<hi; i++){
        int w = g_sent[i];
        float w0 = g_w0[i];
        float w1 = (w & (1<<14)) ? w0 : 0.f;
        float w2 = (w & (1<<15)) ? w0 : 0.f;
        float2 v = ((const float2*)(g_Z + (size_t)(w & 0x3FFF)*DD))[lane];
        a1x += w1*v.x; a1y += w1*v.y;
        a2x += w2*v.x; a2y += w2*v.y;
    }
    ((float2*)(g_AZ1 + (size_t)warp*DD))[lane] = make_float2(a1x, a1y);
    ((float2*)(g_AZ2 + (size_t)warp*DD))[lane] = make_float2(a2x, a2y);
}

// ---------------- small GEMM: C[N,64] = SRC[N,64] @ B ------------------------
template<bool BT, bool BIAS>
__global__ void k_gemm(int srcId, const float* __restrict__ B,
                       const float* __restrict__ bias, int dstId){
    const float* __restrict__ Am = mat_src(srcId);
    float* __restrict__ Cm = mat_dst(dstId);
    __shared__ float Bs[DD*DD];
    __shared__ float As[64*DD];
    int t = threadIdx.x;  // 256
    for (int x=t; x<DD*DD; x+=256){
        int j = x / DD, i = x % DD;
        Bs[x] = BT ? B[i*DD + j] : B[j*DD + i];
    }
    int r0 = blockIdx.x * 64;
    for (int x=t; x<64*DD; x+=256) As[x] = Am[(size_t)r0*DD + x];
    __syncthreads();
    int rl = t >> 2;
    int cg = (t & 3) * 16;
    float acc[16];
    #pragma unroll
    for (int i=0;i<16;i++) acc[i] = BIAS ? bias[cg+i] : 0.f;
    for (int j=0;j<DD;j++){
        float a = As[rl*DD + j];
        #pragma unroll
        for (int i=0;i<16;i++) acc[i] += a * Bs[j*DD + cg + i];
    }
    #pragma unroll
    for (int i=0;i<16;i++) Cm[(size_t)(r0+rl)*DD + cg + i] = acc[i];
}

// three independent fc GEMMs in one launch: blockIdx.y picks motif
__global__ void k_gemm3(const float* __restrict__ fc0, const float* __restrict__ fc1,
                        const float* __restrict__ fc2){
    int y = blockIdx.y;
    const float* __restrict__ B  = (y==0) ? fc0 : (y==1 ? fc1 : fc2);
    const float* __restrict__ Am = mat_src(1 + y);      // g_Z / g_AZ1 / g_AZ2
    float* __restrict__ Cm       = mat_dst(1 + y);      // g_ft0 / g_ft1 / g_ft2
    __shared__ float Bs[DD*DD];
    __shared__ float As[64*DD];
    int t = threadIdx.x;
    for (int x=t; x<DD*DD; x+=256){
        int j = x / DD, i = x % DD;
        Bs[x] = B[j*DD + i];
    }
    int r0 = blockIdx.x * 64;
    for (int x=t; x<64*DD; x+=256) As[x] = Am[(size_t)r0*DD + x];
    __syncthreads();
    int rl = t >> 2;
    int cg = (t & 3) * 16;
    float acc[16];
    #pragma unroll
    for (int i=0;i<16;i++) acc[i] = 0.f;
    for (int j=0;j<DD;j++){
        float a = As[rl*DD + j];
        #pragma unroll
        for (int i=0;i<16;i++) acc[i] += a * Bs[j*DD + cg + i];
    }
    #pragma unroll
    for (int i=0;i<16;i++) Cm[(size_t)(r0+rl)*DD + cg + i] = acc[i];
}

// ---------------- fused single-pass attention (all 3 motifs) -----------------
#define ONLINE_UPD(m, den, ax, ay, p, vx, vy) do {       \
    float _mn = fmaxf((m), (p));                         \
    float _sc = __expf((m) - _mn);                       \
    float _w  = __expf((p) - _mn);                       \
    (den) = (den)*_sc + _w;                              \
    (ax)  = (ax)*_sc + _w*(vx);                          \
    (ay)  = (ay)*_sc + _w*(vy);                          \
    (m) = _mn;                                           \
} while(0)

__global__ void k_attn(){
    __shared__ float sacc[3*DD];
    int t = threadIdx.x;
    for (int j=t; j<3*DD; j+=256) sacc[j] = 0.f;
    __syncthreads();
    int lane = t & 31;
    int gw = (blockIdx.x*256 + t) >> 5;
    const int NW = 512*8;
    for (int d = gw; d < NN; d += NW){
        int lo = g_offd[d], hi = g_offd[d+1];
        if (lo == hi) continue;
        float2 f0 = ((const float2*)(g_ft0 + (size_t)d*DD))[lane];
        float2 f1 = ((const float2*)(g_ft1 + (size_t)d*DD))[lane];
        float2 f2 = ((const float2*)(g_ft2 + (size_t)d*DD))[lane];
        float m0=-FLT_MAX, den0=0.f, a0x=0.f, a0y=0.f;
        float m1=-FLT_MAX, den1=0.f, a1x=0.f, a1y=0.f;
        float m2=-FLT_MAX, den2=0.f, a2x=0.f, a2y=0.f;
        for (int i=lo; i<hi; i++){
            int w = g_dent[i];            // warp-uniform broadcast
            int s = w & 0x3FFF;
            float2 v0 = ((const float2*)(g_ft0 + (size_t)s*DD))[lane];
            float p0 = v0.x*f0.x + v0.y*f0.y;
            #pragma unroll
            for (int o=16;o;o>>=1) p0 += __shfl_xor_sync(0xffffffffu, p0, o);
            p0 *= 0.125f;
            ONLINE_UPD(m0, den0, a0x, a0y, p0, v0.x, v0.y);
            if (w & (1<<14)){
                float2 v1 = ((const float2*)(g_ft1 + (size_t)s*DD))[lane];
                float p1 = v1.x*f1.x + v1.y*f1.y;
                #pragma unroll
                for (int o=16;o;o>>=1) p1 += __shfl_xor_sync(0xffffffffu, p1, o);
                p1 *= 0.125f;
                ONLINE_UPD(m1, den1, a1x, a1y, p1, v1.x, v1.y);
                if (lane == 0){ g_nm1[s] = 1; g_nm1[d] = 1; }
            }
            if (w & (1<<15)){
                float2 v2 = ((const float2*)(g_ft2 + (size_t)s*DD))[lane];
                float p2 = v2.x*f2.x + v2.y*f2.y;
                #pragma unroll
                for (int o=16;o;o>>=1) p2 += __shfl_xor_sync(0xffffffffu, p2, o);
                p2 *= 0.125f;
                ONLINE_UPD(m2, den2, a2x, a2y, p2, v2.x, v2.y);
                if (lane == 0){ g_nm2[s] = 1; g_nm2[d] = 1; }
            }
        }
        atomicAdd(&sacc[       2*lane  ], a0x/fmaxf(den0, 1e-9f));
        atomicAdd(&sacc[       2*lane+1], a0y/fmaxf(den0, 1e-9f));
        if (den1 > 0.f){
            atomicAdd(&sacc[DD   + 2*lane  ], a1x/den1);
            atomicAdd(&sacc[DD   + 2*lane+1], a1y/den1);
        }
        if (den2 > 0.f){
            atomicAdd(&sacc[2*DD + 2*lane  ], a2x/den2);
            atomicAdd(&sacc[2*DD + 2*lane+1], a2y/den2);
        }
    }
    __syncthreads();
    for (int j=t; j<3*DD; j+=256) atomicAdd(&g_pool[j], sacc[j]);
}

// ---------------- node counts + final linear (fused, one block) --------------
__global__ void k_nfinal(const float* __restrict__ lw, const float* __restrict__ lb,
                         float* __restrict__ out){
    __shared__ int sc1, sc2;
    __shared__ float s0[3*DD], s1[3*DD];
    int t = threadIdx.x;   // 256
    if (t == 0){ sc1 = 0; sc2 = 0; }
    __syncthreads();
    int c1 = 0, c2 = 0;
    for (int i=t; i<NN; i+=256){ c1 += g_nm1[i]; c2 += g_nm2[i]; }
    #pragma unroll
    for (int o=16;o;o>>=1){
        c1 += __shfl_xor_sync(0xffffffffu, c1, o);
        c2 += __shfl_xor_sync(0xffffffffu, c2, o);
    }
    if ((t & 31) == 0){ atomicAdd(&sc1, c1); atomicAdd(&sc2, c2); }
    __syncthreads();
    if (t < 3*DD){
        int k = t >> 6;
        float cnt = (k==0) ? (float)NN : fmaxf((float)(k==1 ? sc1 : sc2), 1.f);
        float p = g_pool[t] / cnt;
        s0[t] = p * lw[t*2 + 0];
        s1[t] = p * lw[t*2 + 1];
    }
    __syncthreads();
    if (t == 0){
        float a = 0.f, b = 0.f;
        for (int i=0;i<3*DD;i++){ a += s0[i]; b += s1[i]; }
        out[0] = a + lb[0];
        out[1] = b + lb[1];
    }
}

// ---------------- host launcher -----------------------------------------------
extern "C" void kernel_launch(void* const* d_in, const int* in_sizes, int n_in,
                              void* d_out, int out_size){
    const float* h    = (const float*)d_in[0];
    const float* A1   = (const float*)d_in[2];
    const float* A2   = (const float*)d_in[3];
    const float* Ww   = (const float*)d_in[4];
    const float* Wb   = (const float*)d_in[5];
    const float* fc0  = (const float*)d_in[6];
    const float* fc1  = (const float*)d_in[7];
    const float* fc2  = (const float*)d_in[8];
    const float* linw = (const float*)d_in[9];
    const float* linb = (const float*)d_in[10];
    const int*   src  = (const int*)d_in[11];
    const int*   dst  = (const int*)d_in[12];
    float* out = (float*)d_out;

    k_init   <<<64,   256>>>();
    k_hist   <<<2048, 256>>>(src, dst);
    k_scan   <<<2,   1024>>>();
    k_scatter<<<2048, 256>>>(src, dst, A1, A2);
    k_aggH   <<<1024, 256>>>(h);                              // + dedup weights
    k_gemm<true, true><<<128, 256>>>(0, Ww, Wb, 0);           // g_Z = g_AH @ Ww.T + Wb
    k_aggZ   <<<1024, 256>>>();
    dim3 g3(128, 3);
    k_gemm3  <<<g3,   256>>>(fc0, fc1, fc2);                  // ft0/ft1/ft2
    k_attn   <<<512,  256>>>();
    k_nfinal <<<1,    256>>>(linw, linb, out);
    (void)in_sizes; (void)n_in; (void)out_size;
}

// round 6
// speedup vs baseline: 2.1885x; 1.1949x over previous
#include <cuda_runtime.h>
#include <math.h>
#include <float.h>

#define NN 8192
#define DD 64
#define EE 524288

// ---------------- static device scratch -------------------------------------
__device__ float g_Z  [NN*DD];
__device__ float g_ft0[NN*DD];
__device__ float g_ft1[NN*DD];
__device__ float g_ft2[NN*DD];
__device__ float g_w0 [EE];            // 1/multiplicity, src-CSR order
__device__ int   g_sent[EE];           // src-CSR entries: dst | m1<<14 | m2<<15
__device__ int   g_dent[EE];           // dst-CSR entries: src | m1<<14 | m2<<15
__device__ int   g_hists[NN], g_histd[NN];
__device__ int   g_offs[NN+1], g_offd[NN+1];
__device__ int   g_curs[NN],  g_curd[NN];
__device__ int   g_nm1[NN], g_nm2[NN];
__device__ float g_pool[3*DD];

// ---------------- init -------------------------------------------------------
__global__ void k_init(){
    int i = blockIdx.x*blockDim.x + threadIdx.x;
    int T = gridDim.x*blockDim.x;
    for (int j=i; j<NN; j+=T){ g_hists[j]=0; g_histd[j]=0; g_nm1[j]=0; g_nm2[j]=0; }
    if (i < 3*DD) g_pool[i] = 0.f;
}

// ---------------- CSR builds (both directions) -------------------------------
__global__ void k_hist(const int* __restrict__ src, const int* __restrict__ dst){
    int e2 = blockIdx.x*blockDim.x + threadIdx.x;   // handles edges 2e2, 2e2+1
    if (e2 >= EE/2) return;
    int2 s = ((const int2*)src)[e2];
    int2 d = ((const int2*)dst)[e2];
    atomicAdd(&g_hists[s.x], 1); atomicAdd(&g_hists[s.y], 1);
    atomicAdd(&g_histd[d.x], 1); atomicAdd(&g_histd[d.y], 1);
}

__global__ void k_scan(){  // blockIdx 0 -> src CSR, 1 -> dst CSR
    int* hist = blockIdx.x ? g_histd : g_hists;
    int* off  = blockIdx.x ? g_offd  : g_offs;
    int* cur  = blockIdx.x ? g_curd  : g_curs;
    __shared__ int s[1024];
    int t = threadIdx.x;
    int base = t*8;
    int loc[8]; int sum = 0;
    #pragma unroll
    for (int i=0;i<8;i++){ loc[i]=sum; sum += hist[base+i]; }
    s[t] = sum;
    __syncthreads();
    for (int off2=1; off2<1024; off2<<=1){
        int v = (t>=off2) ? s[t-off2] : 0;
        __syncthreads();
        s[t] += v;
        __syncthreads();
    }
    int ex = (t==0) ? 0 : s[t-1];
    #pragma unroll
    for (int i=0;i<8;i++){ int o = ex + loc[i]; off[base+i]=o; cur[base+i]=o; }
    if (t == 1023) off[NN] = ex + sum;
}

// scatter + motif mask gather fused; 2 edges/thread for MLP
__global__ void k_scatter(const int* __restrict__ src, const int* __restrict__ dst,
                          const float* __restrict__ A1, const float* __restrict__ A2){
    int e2 = blockIdx.x*blockDim.x + threadIdx.x;
    if (e2 >= EE/2) return;
    int2 s = ((const int2*)src)[e2];
    int2 d = ((const int2*)dst)[e2];
    float a1x = __ldcs(&A1[(size_t)s.x*NN + d.x]);
    float a2x = __ldcs(&A2[(size_t)s.x*NN + d.x]);
    float a1y = __ldcs(&A1[(size_t)s.y*NN + d.y]);
    float a2y = __ldcs(&A2[(size_t)s.y*NN + d.y]);
    int bx = ((a1x > 0.f) ? (1<<14) : 0) | ((a2x > 0.f) ? (1<<15) : 0);
    int by = ((a1y > 0.f) ? (1<<14) : 0) | ((a2y > 0.f) ? (1<<15) : 0);
    g_sent[atomicAdd(&g_curs[s.x], 1)] = d.x | bx;
    g_dent[atomicAdd(&g_curd[d.x], 1)] = s.x | bx;
    g_sent[atomicAdd(&g_curs[s.y], 1)] = d.y | by;
    g_dent[atomicAdd(&g_curd[d.y], 1)] = s.y | by;
}

// ---------------- k1: dedup weights + AH gather + Z = AH@Ww.T+Wb + ft0=Z@fc0 --
__global__ void k1(const float* __restrict__ h, const float* __restrict__ Ww,
                   const float* __restrict__ Wb, const float* __restrict__ fc0){
    __shared__ float sW[DD*DD];     // sW[k*64+j] = Ww[j][k]
    __shared__ float sF[DD*DD];     // fc0 natural layout [k][j]
    __shared__ int   sd [8*512];
    __shared__ float srow[8][DD];
    int t = threadIdx.x;            // 256
    for (int x=t; x<DD*DD; x+=256){
        int k = x >> 6, j = x & 63;
        sW[x] = Ww[j*DD + k];
        sF[x] = fc0[x];
    }
    __syncthreads();
    int wl   = t >> 5;
    int lane = t & 31;
    int row  = blockIdx.x*8 + wl;
    int lo = g_offs[row], hi = g_offs[row+1];
    int L = hi - lo;
    float ax=0.f, ay=0.f;
    int*   my = sd + wl*512;
    if (L <= 512){
        for (int i=lane; i<L; i+=32) my[i] = g_sent[lo+i];
        __syncwarp();
        for (int i=lane; i<L; i+=32){
            int dv = my[i] & 0x3FFF; int c = 0;
            for (int j=0;j<L;j++) c += ((my[j]&0x3FFF)==dv);
            g_w0[lo+i] = 1.f/(float)c;
        }
        __syncwarp();
        for (int i=0; i<L; i++){
            float w0 = g_w0[lo+i];
            float2 v = ((const float2*)(h + (size_t)(my[i] & 0x3FFF)*DD))[lane];
            ax += w0*v.x; ay += w0*v.y;
        }
    } else {
        for (int i=lane; i<L; i+=32){
            int dv = g_sent[lo+i] & 0x3FFF; int c = 0;
            for (int j=0;j<L;j++) c += ((g_sent[lo+j]&0x3FFF)==dv);
            g_w0[lo+i] = 1.f/(float)c;
        }
        __syncwarp();
        for (int i=lo; i<hi; i++){
            float w0 = g_w0[i];
            float2 v = ((const float2*)(h + (size_t)(g_sent[i] & 0x3FFF)*DD))[lane];
            ax += w0*v.x; ay += w0*v.y;
        }
    }
    // stage AH row, matvec with Ww.T -> Z row
    srow[wl][2*lane] = ax; srow[wl][2*lane+1] = ay;
    __syncwarp();
    float2 z = ((const float2*)Wb)[lane];
    #pragma unroll 8
    for (int k=0;k<DD;k++){
        float a = srow[wl][k];
        float2 wv = ((const float2*)(sW + k*DD))[lane];
        z.x += a*wv.x; z.y += a*wv.y;
    }
    ((float2*)(g_Z + (size_t)row*DD))[lane] = z;
    __syncwarp();
    srow[wl][2*lane] = z.x; srow[wl][2*lane+1] = z.y;
    __syncwarp();
    float2 f = make_float2(0.f, 0.f);
    #pragma unroll 8
    for (int k=0;k<DD;k++){
        float a = srow[wl][k];
        float2 wv = ((const float2*)(sF + k*DD))[lane];
        f.x += a*wv.x; f.y += a*wv.y;
    }
    ((float2*)(g_ft0 + (size_t)row*DD))[lane] = f;
}

// ---------------- k2: AZ1/AZ2 gather + ft1=AZ1@fc1, ft2=AZ2@fc2 --------------
__global__ void k2(const float* __restrict__ fc1, const float* __restrict__ fc2){
    __shared__ float sF1[DD*DD];
    __shared__ float sF2[DD*DD];
    __shared__ float srow[8][2*DD];
    int t = threadIdx.x;   // 256
    for (int x=t; x<DD*DD; x+=256){ sF1[x] = fc1[x]; sF2[x] = fc2[x]; }
    __syncthreads();
    int wl   = t >> 5;
    int lane = t & 31;
    int row  = blockIdx.x*8 + wl;
    int lo = g_offs[row], hi = g_offs[row+1];
    float a1x=0.f,a1y=0.f,a2x=0.f,a2y=0.f;
    for (int i=lo; i<hi; i++){
        int w = g_sent[i];
        float w0 = g_w0[i];
        float w1 = (w & (1<<14)) ? w0 : 0.f;
        float w2 = (w & (1<<15)) ? w0 : 0.f;
        float2 v = ((const float2*)(g_Z + (size_t)(w & 0x3FFF)*DD))[lane];
        a1x += w1*v.x; a1y += w1*v.y;
        a2x += w2*v.x; a2y += w2*v.y;
    }
    srow[wl][2*lane]      = a1x; srow[wl][2*lane+1]      = a1y;
    srow[wl][DD+2*lane]   = a2x; srow[wl][DD+2*lane+1]   = a2y;
    __syncwarp();
    float2 f1 = make_float2(0.f,0.f), f2 = make_float2(0.f,0.f);
    #pragma unroll 8
    for (int k=0;k<DD;k++){
        float a1 = srow[wl][k];
        float a2 = srow[wl][DD+k];
        float2 w1 = ((const float2*)(sF1 + k*DD))[lane];
        float2 w2 = ((const float2*)(sF2 + k*DD))[lane];
        f1.x += a1*w1.x; f1.y += a1*w1.y;
        f2.x += a2*w2.x; f2.y += a2*w2.y;
    }
    ((float2*)(g_ft1 + (size_t)row*DD))[lane] = f1;
    ((float2*)(g_ft2 + (size_t)row*DD))[lane] = f2;
}

// ---------------- fused single-pass attention (all 3 motifs) -----------------
// 16-lane sub-warp per dst row; float4 per lane; online softmax.
// CRITICAL: shuffles use the 16-lane GROUP mask — the two half-warps diverge
// (different rows / edge counts), full-warp-mask sync would deadlock.
#define ONLINE_UPD4(m, den, acc, p, v) do {              \
    float _mn = fmaxf((m), (p));                         \
    float _sc = __expf((m) - _mn);                       \
    float _w  = __expf((p) - _mn);                       \
    (den) = (den)*_sc + _w;                              \
    (acc).x = (acc).x*_sc + _w*(v).x;                    \
    (acc).y = (acc).y*_sc + _w*(v).y;                    \
    (acc).z = (acc).z*_sc + _w*(v).z;                    \
    (acc).w = (acc).w*_sc + _w*(v).w;                    \
    (m) = _mn;                                           \
} while(0)

__device__ __forceinline__ float red16(float p, unsigned gmask){
    #pragma unroll
    for (int o=8;o;o>>=1) p += __shfl_xor_sync(gmask, p, o);
    return p;
}

__global__ void k_attn(){
    __shared__ float sacc[3*DD];
    int t = threadIdx.x;
    for (int j=t; j<3*DD; j+=256) sacc[j] = 0.f;
    __syncthreads();
    int hl = t & 15;                                 // lane within 16-group
    unsigned gmask = 0xFFFFu << (t & 16);            // this half-warp's mask
    int d  = (blockIdx.x*256 + t) >> 4;              // one dst row per half-warp
    if (d < NN){
        int lo = g_offd[d], hi = g_offd[d+1];
        if (lo < hi){
            float4 f0 = ((const float4*)(g_ft0 + (size_t)d*DD))[hl];
            float4 f1 = ((const float4*)(g_ft1 + (size_t)d*DD))[hl];
            float4 f2 = ((const float4*)(g_ft2 + (size_t)d*DD))[hl];
            float m0=-FLT_MAX, den0=0.f; float4 a0 = make_float4(0,0,0,0);
            float m1=-FLT_MAX, den1=0.f; float4 a1 = make_float4(0,0,0,0);
            float m2=-FLT_MAX, den2=0.f; float4 a2 = make_float4(0,0,0,0);
            for (int i=lo; i<hi; i++){
                int w = g_dent[i];                    // group-uniform
                int s = w & 0x3FFF;
                float4 v0 = ((const float4*)(g_ft0 + (size_t)s*DD))[hl];
                float p0 = red16(v0.x*f0.x + v0.y*f0.y + v0.z*f0.z + v0.w*f0.w, gmask) * 0.125f;
                ONLINE_UPD4(m0, den0, a0, p0, v0);
                if (w & (1<<14)){
                    float4 v1 = ((const float4*)(g_ft1 + (size_t)s*DD))[hl];
                    float p1 = red16(v1.x*f1.x + v1.y*f1.y + v1.z*f1.z + v1.w*f1.w, gmask) * 0.125f;
                    ONLINE_UPD4(m1, den1, a1, p1, v1);
                    if (hl == 0){ g_nm1[s] = 1; g_nm1[d] = 1; }
                }
                if (w & (1<<15)){
                    float4 v2 = ((const float4*)(g_ft2 + (size_t)s*DD))[hl];
                    float p2 = red16(v2.x*f2.x + v2.y*f2.y + v2.z*f2.z + v2.w*f2.w, gmask) * 0.125f;
                    ONLINE_UPD4(m2, den2, a2, p2, v2);
                    if (hl == 0){ g_nm2[s] = 1; g_nm2[d] = 1; }
                }
            }
            float r0 = 1.f/fmaxf(den0, 1e-9f);
            atomicAdd(&sacc[4*hl+0], a0.x*r0); atomicAdd(&sacc[4*hl+1], a0.y*r0);
            atomicAdd(&sacc[4*hl+2], a0.z*r0); atomicAdd(&sacc[4*hl+3], a0.w*r0);
            if (den1 > 0.f){
                float r1 = 1.f/den1;
                atomicAdd(&sacc[DD+4*hl+0], a1.x*r1); atomicAdd(&sacc[DD+4*hl+1], a1.y*r1);
                atomicAdd(&sacc[DD+4*hl+2], a1.z*r1); atomicAdd(&sacc[DD+4*hl+3], a1.w*r1);
            }
            if (den2 > 0.f){
                float r2 = 1.f/den2;
                atomicAdd(&sacc[2*DD+4*hl+0], a2.x*r2); atomicAdd(&sacc[2*DD+4*hl+1], a2.y*r2);
                atomicAdd(&sacc[2*DD+4*hl+2], a2.z*r2); atomicAdd(&sacc[2*DD+4*hl+3], a2.w*r2);
            }
        }
    }
    __syncthreads();
    for (int j=t; j<3*DD; j+=256) atomicAdd(&g_pool[j], sacc[j]);
}

// ---------------- node counts + final linear (fused, one block) --------------
__global__ void k_nfinal(const float* __restrict__ lw, const float* __restrict__ lb,
                         float* __restrict__ out){
    __shared__ int sc1, sc2;
    __shared__ float s0[3*DD], s1[3*DD];
    int t = threadIdx.x;   // 256
    if (t == 0){ sc1 = 0; sc2 = 0; }
    __syncthreads();
    int c1 = 0, c2 = 0;
    for (int i=t; i<NN; i+=256){ c1 += g_nm1[i]; c2 += g_nm2[i]; }
    #pragma unroll
    for (int o=16;o;o>>=1){
        c1 += __shfl_xor_sync(0xffffffffu, c1, o);
        c2 += __shfl_xor_sync(0xffffffffu, c2, o);
    }
    if ((t & 31) == 0){ atomicAdd(&sc1, c1); atomicAdd(&sc2, c2); }
    __syncthreads();
    if (t < 3*DD){
        int k = t >> 6;
        float cnt = (k==0) ? (float)NN : fmaxf((float)(k==1 ? sc1 : sc2), 1.f);
        float p = g_pool[t] / cnt;
        s0[t] = p * lw[t*2 + 0];
        s1[t] = p * lw[t*2 + 1];
    }
    __syncthreads();
    if (t == 0){
        float a = 0.f, b = 0.f;
        for (int i=0;i<3*DD;i++){ a += s0[i]; b += s1[i]; }
        out[0] = a + lb[0];
        out[1] = b + lb[1];
    }
}

// ---------------- host launcher -----------------------------------------------
extern "C" void kernel_launch(void* const* d_in, const int* in_sizes, int n_in,
                              void* d_out, int out_size){
    const float* h    = (const float*)d_in[0];
    const float* A1   = (const float*)d_in[2];
    const float* A2   = (const float*)d_in[3];
    const float* Ww   = (const float*)d_in[4];
    const float* Wb   = (const float*)d_in[5];
    const float* fc0  = (const float*)d_in[6];
    const float* fc1  = (const float*)d_in[7];
    const float* fc2  = (const float*)d_in[8];
    const float* linw = (const float*)d_in[9];
    const float* linb = (const float*)d_in[10];
    const int*   src  = (const int*)d_in[11];
    const int*   dst  = (const int*)d_in[12];
    float* out = (float*)d_out;

    k_init   <<<64,   256>>>();
    k_hist   <<<1024, 256>>>(src, dst);
    k_scan   <<<2,   1024>>>();
    k_scatter<<<1024, 256>>>(src, dst, A1, A2);
    k1       <<<1024, 256>>>(h, Ww, Wb, fc0);   // dedup + AH + Z + ft0
    k2       <<<1024, 256>>>(fc1, fc2);         // AZ1/AZ2 + ft1 + ft2
    k_attn   <<<512,  256>>>();
    k_nfinal <<<1,    256>>>(linw, linb, out);
    (void)in_sizes; (void)n_in; (void)out_size;
}

// round 7
// speedup vs baseline: 2.2409x; 1.0240x over previous
#include <cuda_runtime.h>
#include <math.h>
#include <float.h>

#define NN 8192
#define DD 64
#define EE 524288

// ---------------- static device scratch -------------------------------------
__device__ float g_Z  [NN*DD];
__device__ float g_ft0[NN*DD];
__device__ float g_ft1[NN*DD];
__device__ float g_ft2[NN*DD];
__device__ float g_w0 [EE];            // 1/multiplicity, src-CSR order
__device__ int   g_sent[EE];           // src-CSR entries: dst | m1<<14 | m2<<15
__device__ int   g_dent[EE];           // dst-CSR entries: src | m1<<14 | m2<<15
__device__ unsigned char g_bits[EE];   // per-edge motif bits (1|2)
__device__ int   g_hists[NN], g_histd[NN];
__device__ int   g_offs[NN+1], g_offd[NN+1];
__device__ int   g_curs[NN],  g_curd[NN];
__device__ int   g_nm1[NN], g_nm2[NN];
__device__ float g_pool[3*DD];

// ---------------- init -------------------------------------------------------
__global__ void k_init(){
    int i = blockIdx.x*blockDim.x + threadIdx.x;
    int T = gridDim.x*blockDim.x;
    for (int j=i; j<NN; j+=T){ g_hists[j]=0; g_histd[j]=0; g_nm1[j]=0; g_nm2[j]=0; }
    if (i < 3*DD) g_pool[i] = 0.f;
}

// ---------------- hist + A1/A2 mask gather (latency overlap) ------------------
__global__ void k_hist(const int* __restrict__ src, const int* __restrict__ dst,
                       const float* __restrict__ A1, const float* __restrict__ A2){
    int e2 = blockIdx.x*blockDim.x + threadIdx.x;   // edges 2e2, 2e2+1
    if (e2 >= EE/2) return;
    int2 s = ((const int2*)src)[e2];
    int2 d = ((const int2*)dst)[e2];
    size_t ix = (size_t)s.x*NN + d.x;
    size_t iy = (size_t)s.y*NN + d.y;
    float a1x = __ldcs(&A1[ix]);
    float a2x = __ldcs(&A2[ix]);
    float a1y = __ldcs(&A1[iy]);
    float a2y = __ldcs(&A2[iy]);
    atomicAdd(&g_hists[s.x], 1); atomicAdd(&g_hists[s.y], 1);
    atomicAdd(&g_histd[d.x], 1); atomicAdd(&g_histd[d.y], 1);
    uchar2 b;
    b.x = (unsigned char)(((a1x > 0.f) ? 1 : 0) | ((a2x > 0.f) ? 2 : 0));
    b.y = (unsigned char)(((a1y > 0.f) ? 1 : 0) | ((a2y > 0.f) ? 2 : 0));
    ((uchar2*)g_bits)[e2] = b;
}

__global__ void k_scan(){  // blockIdx 0 -> src CSR, 1 -> dst CSR
    int* hist = blockIdx.x ? g_histd : g_hists;
    int* off  = blockIdx.x ? g_offd  : g_offs;
    int* cur  = blockIdx.x ? g_curd  : g_curs;
    __shared__ int s[1024];
    int t = threadIdx.x;
    int base = t*8;
    int loc[8]; int sum = 0;
    #pragma unroll
    for (int i=0;i<8;i++){ loc[i]=sum; sum += hist[base+i]; }
    s[t] = sum;
    __syncthreads();
    for (int off2=1; off2<1024; off2<<=1){
        int v = (t>=off2) ? s[t-off2] : 0;
        __syncthreads();
        s[t] += v;
        __syncthreads();
    }
    int ex = (t==0) ? 0 : s[t-1];
    #pragma unroll
    for (int i=0;i<8;i++){ int o = ex + loc[i]; off[base+i]=o; cur[base+i]=o; }
    if (t == 1023) off[NN] = ex + sum;
}

// scatter: atomics + stores only (A gathers already done in k_hist)
__global__ void k_scatter(const int* __restrict__ src, const int* __restrict__ dst){
    int e2 = blockIdx.x*blockDim.x + threadIdx.x;
    if (e2 >= EE/2) return;
    int2 s = ((const int2*)src)[e2];
    int2 d = ((const int2*)dst)[e2];
    uchar2 b = ((const uchar2*)g_bits)[e2];
    int bx = ((int)b.x) << 14;
    int by = ((int)b.y) << 14;
    g_sent[atomicAdd(&g_curs[s.x], 1)] = d.x | bx;
    g_dent[atomicAdd(&g_curd[d.x], 1)] = s.x | bx;
    g_sent[atomicAdd(&g_curs[s.y], 1)] = d.y | by;
    g_dent[atomicAdd(&g_curd[d.y], 1)] = s.y | by;
}

// ---------------- k1: dedup weights + AH gather + Z = AH@Ww.T+Wb + ft0=Z@fc0 --
__global__ void k1(const float* __restrict__ h, const float* __restrict__ Ww,
                   const float* __restrict__ Wb, const float* __restrict__ fc0){
    __shared__ float sW[DD*DD];     // sW[k*64+j] = Ww[j][k]
    __shared__ float sF[DD*DD];     // fc0 natural layout [k][j]
    __shared__ int   sd [8*512];
    __shared__ float srow[8][DD];
    int t = threadIdx.x;            // 256
    for (int x=t; x<DD*DD; x+=256){
        int k = x >> 6, j = x & 63;
        sW[x] = Ww[j*DD + k];
        sF[x] = fc0[x];
    }
    __syncthreads();
    int wl   = t >> 5;
    int lane = t & 31;
    int row  = blockIdx.x*8 + wl;
    int lo = g_offs[row], hi = g_offs[row+1];
    int L = hi - lo;
    float ax=0.f, ay=0.f;
    int*   my = sd + wl*512;
    if (L <= 512){
        for (int i=lane; i<L; i+=32) my[i] = g_sent[lo+i];
        __syncwarp();
        for (int i=lane; i<L; i+=32){
            int dv = my[i] & 0x3FFF; int c = 0;
            for (int j=0;j<L;j++) c += ((my[j]&0x3FFF)==dv);
            g_w0[lo+i] = 1.f/(float)c;
        }
        __syncwarp();
        #pragma unroll 4
        for (int i=0; i<L; i++){
            float w0 = g_w0[lo+i];
            float2 v = ((const float2*)(h + (size_t)(my[i] & 0x3FFF)*DD))[lane];
            ax += w0*v.x; ay += w0*v.y;
        }
    } else {
        for (int i=lane; i<L; i+=32){
            int dv = g_sent[lo+i] & 0x3FFF; int c = 0;
            for (int j=0;j<L;j++) c += ((g_sent[lo+j]&0x3FFF)==dv);
            g_w0[lo+i] = 1.f/(float)c;
        }
        __syncwarp();
        for (int i=lo; i<hi; i++){
            float w0 = g_w0[i];
            float2 v = ((const float2*)(h + (size_t)(g_sent[i] & 0x3FFF)*DD))[lane];
            ax += w0*v.x; ay += w0*v.y;
        }
    }
    // stage AH row, matvec with Ww.T -> Z row
    srow[wl][2*lane] = ax; srow[wl][2*lane+1] = ay;
    __syncwarp();
    float2 z = ((const float2*)Wb)[lane];
    #pragma unroll 8
    for (int k=0;k<DD;k++){
        float a = srow[wl][k];
        float2 wv = ((const float2*)(sW + k*DD))[lane];
        z.x += a*wv.x; z.y += a*wv.y;
    }
    ((float2*)(g_Z + (size_t)row*DD))[lane] = z;
    __syncwarp();
    srow[wl][2*lane] = z.x; srow[wl][2*lane+1] = z.y;
    __syncwarp();
    float2 f = make_float2(0.f, 0.f);
    #pragma unroll 8
    for (int k=0;k<DD;k++){
        float a = srow[wl][k];
        float2 wv = ((const float2*)(sF + k*DD))[lane];
        f.x += a*wv.x; f.y += a*wv.y;
    }
    ((float2*)(g_ft0 + (size_t)row*DD))[lane] = f;
}

// ---------------- k2: AZ1/AZ2 gather + ft1=AZ1@fc1, ft2=AZ2@fc2 --------------
__global__ void k2(const float* __restrict__ fc1, const float* __restrict__ fc2){
    __shared__ float sF1[DD*DD];
    __shared__ float sF2[DD*DD];
    __shared__ float srow[8][2*DD];
    int t = threadIdx.x;   // 256
    for (int x=t; x<DD*DD; x+=256){ sF1[x] = fc1[x]; sF2[x] = fc2[x]; }
    __syncthreads();
    int wl   = t >> 5;
    int lane = t & 31;
    int row  = blockIdx.x*8 + wl;
    int lo = g_offs[row], hi = g_offs[row+1];
    float a1x=0.f,a1y=0.f,a2x=0.f,a2y=0.f;
    #pragma unroll 4
    for (int i=lo; i<hi; i++){
        int w = g_sent[i];
        float w0 = g_w0[i];
        float w1 = (w & (1<<14)) ? w0 : 0.f;
        float w2 = (w & (1<<15)) ? w0 : 0.f;
        float2 v = ((const float2*)(g_Z + (size_t)(w & 0x3FFF)*DD))[lane];
        a1x += w1*v.x; a1y += w1*v.y;
        a2x += w2*v.x; a2y += w2*v.y;
    }
    srow[wl][2*lane]      = a1x; srow[wl][2*lane+1]      = a1y;
    srow[wl][DD+2*lane]   = a2x; srow[wl][DD+2*lane+1]   = a2y;
    __syncwarp();
    float2 f1 = make_float2(0.f,0.f), f2 = make_float2(0.f,0.f);
    #pragma unroll 8
    for (int k=0;k<DD;k++){
        float a1 = srow[wl][k];
        float a2 = srow[wl][DD+k];
        float2 w1 = ((const float2*)(sF1 + k*DD))[lane];
        float2 w2 = ((const float2*)(sF2 + k*DD))[lane];
        f1.x += a1*w1.x; f1.y += a1*w1.y;
        f2.x += a2*w2.x; f2.y += a2*w2.y;
    }
    ((float2*)(g_ft1 + (size_t)row*DD))[lane] = f1;
    ((float2*)(g_ft2 + (size_t)row*DD))[lane] = f2;
}

// ---------------- fused single-pass attention (all 3 motifs) -----------------
// 16-lane sub-warp per dst row; float4 per lane; online softmax; motif-0 path
// unrolled by 2 for MLP. Shuffles MUST use the 16-lane group mask.
#define ONLINE_UPD4(m, den, acc, p, v) do {              \
    float _mn = fmaxf((m), (p));                         \
    float _sc = __expf((m) - _mn);                       \
    float _w  = __expf((p) - _mn);                       \
    (den) = (den)*_sc + _w;                              \
    (acc).x = (acc).x*_sc + _w*(v).x;                    \
    (acc).y = (acc).y*_sc + _w*(v).y;                    \
    (acc).z = (acc).z*_sc + _w*(v).z;                    \
    (acc).w = (acc).w*_sc + _w*(v).w;                    \
    (m) = _mn;                                           \
} while(0)

#define ONLINE_UPD4X2(m, den, acc, pa, va, pb, vb) do {  \
    float _mn = fmaxf((m), fmaxf((pa), (pb)));           \
    float _sc = __expf((m) - _mn);                       \
    float _wa = __expf((pa) - _mn);                      \
    float _wb = __expf((pb) - _mn);                      \
    (den) = (den)*_sc + _wa + _wb;                       \
    (acc).x = (acc).x*_sc + _wa*(va).x + _wb*(vb).x;     \
    (acc).y = (acc).y*_sc + _wa*(va).y + _wb*(vb).y;     \
    (acc).z = (acc).z*_sc + _wa*(va).z + _wb*(vb).z;     \
    (acc).w = (acc).w*_sc + _wa*(va).w + _wb*(vb).w;     \
    (m) = _mn;                                           \
} while(0)

__device__ __forceinline__ float red16(float p, unsigned gmask){
    #pragma unroll
    for (int o=8;o;o>>=1) p += __shfl_xor_sync(gmask, p, o);
    return p;
}

__device__ __forceinline__ float dot4(float4 a, float4 b){
    return a.x*b.x + a.y*b.y + a.z*b.z + a.w*b.w;
}

__global__ void k_attn(){
    __shared__ float sacc[3*DD];
    int t = threadIdx.x;
    for (int j=t; j<3*DD; j+=256) sacc[j] = 0.f;
    __syncthreads();
    int hl = t & 15;
    unsigned gmask = 0xFFFFu << (t & 16);
    int d  = (blockIdx.x*256 + t) >> 4;       // one dst row per 16-group
    if (d < NN){
        int lo = g_offd[d], hi = g_offd[d+1];
        if (lo < hi){
            float4 f0 = ((const float4*)(g_ft0 + (size_t)d*DD))[hl];
            float4 f1 = ((const float4*)(g_ft1 + (size_t)d*DD))[hl];
            float4 f2 = ((const float4*)(g_ft2 + (size_t)d*DD))[hl];
            float m0=-FLT_MAX, den0=0.f; float4 a0 = make_float4(0,0,0,0);
            float m1=-FLT_MAX, den1=0.f; float4 a1 = make_float4(0,0,0,0);
            float m2=-FLT_MAX, den2=0.f; float4 a2 = make_float4(0,0,0,0);
            int i = lo;
            for (; i+1 < hi; i += 2){
                int wa = g_dent[i];
                int wb = g_dent[i+1];
                int sa = wa & 0x3FFF, sb = wb & 0x3FFF;
                float4 va = ((const float4*)(g_ft0 + (size_t)sa*DD))[hl];
                float4 vb = ((const float4*)(g_ft0 + (size_t)sb*DD))[hl];
                float pa = red16(dot4(va, f0), gmask) * 0.125f;
                float pb = red16(dot4(vb, f0), gmask) * 0.125f;
                ONLINE_UPD4X2(m0, den0, a0, pa, va, pb, vb);
                if (wa & (1<<14)){
                    float4 v1 = ((const float4*)(g_ft1 + (size_t)sa*DD))[hl];
                    float p1 = red16(dot4(v1, f1), gmask) * 0.125f;
                    ONLINE_UPD4(m1, den1, a1, p1, v1);
                    if (hl == 0){ g_nm1[sa] = 1; g_nm1[d] = 1; }
                }
                if (wb & (1<<14)){
                    float4 v1 = ((const float4*)(g_ft1 + (size_t)sb*DD))[hl];
                    float p1 = red16(dot4(v1, f1), gmask) * 0.125f;
                    ONLINE_UPD4(m1, den1, a1, p1, v1);
                    if (hl == 0){ g_nm1[sb] = 1; g_nm1[d] = 1; }
                }
                if (wa & (1<<15)){
                    float4 v2 = ((const float4*)(g_ft2 + (size_t)sa*DD))[hl];
                    float p2 = red16(dot4(v2, f2), gmask) * 0.125f;
                    ONLINE_UPD4(m2, den2, a2, p2, v2);
                    if (hl == 0){ g_nm2[sa] = 1; g_nm2[d] = 1; }
                }
                if (wb & (1<<15)){
                    float4 v2 = ((const float4*)(g_ft2 + (size_t)sb*DD))[hl];
                    float p2 = red16(dot4(v2, f2), gmask) * 0.125f;
                    ONLINE_UPD4(m2, den2, a2, p2, v2);
                    if (hl == 0){ g_nm2[sb] = 1; g_nm2[d] = 1; }
                }
            }
            if (i < hi){
                int w = g_dent[i];
                int s = w & 0x3FFF;
                float4 v0 = ((const float4*)(g_ft0 + (size_t)s*DD))[hl];
                float p0 = red16(dot4(v0, f0), gmask) * 0.125f;
                ONLINE_UPD4(m0, den0, a0, p0, v0);
                if (w & (1<<14)){
                    float4 v1 = ((const float4*)(g_ft1 + (size_t)s*DD))[hl];
                    float p1 = red16(dot4(v1, f1), gmask) * 0.125f;
                    ONLINE_UPD4(m1, den1, a1, p1, v1);
                    if (hl == 0){ g_nm1[s] = 1; g_nm1[d] = 1; }
                }
                if (w & (1<<15)){
                    float4 v2 = ((const float4*)(g_ft2 + (size_t)s*DD))[hl];
                    float p2 = red16(dot4(v2, f2), gmask) * 0.125f;
                    ONLINE_UPD4(m2, den2, a2, p2, v2);
                    if (hl == 0){ g_nm2[s] = 1; g_nm2[d] = 1; }
                }
            }
            float r0 = 1.f/fmaxf(den0, 1e-9f);
            atomicAdd(&sacc[4*hl+0], a0.x*r0); atomicAdd(&sacc[4*hl+1], a0.y*r0);
            atomicAdd(&sacc[4*hl+2], a0.z*r0); atomicAdd(&sacc[4*hl+3], a0.w*r0);
            if (den1 > 0.f){
                float r1 = 1.f/den1;
                atomicAdd(&sacc[DD+4*hl+0], a1.x*r1); atomicAdd(&sacc[DD+4*hl+1], a1.y*r1);
                atomicAdd(&sacc[DD+4*hl+2], a1.z*r1); atomicAdd(&sacc[DD+4*hl+3], a1.w*r1);
            }
            if (den2 > 0.f){
                float r2 = 1.f/den2;
                atomicAdd(&sacc[2*DD+4*hl+0], a2.x*r2); atomicAdd(&sacc[2*DD+4*hl+1], a2.y*r2);
                atomicAdd(&sacc[2*DD+4*hl+2], a2.z*r2); atomicAdd(&sacc[2*DD+4*hl+3], a2.w*r2);
            }
        }
    }
    __syncthreads();
    for (int j=t; j<3*DD; j+=256) atomicAdd(&g_pool[j], sacc[j]);
}

// ---------------- node counts + final linear (fused, one block) --------------
__global__ void k_nfinal(const float* __restrict__ lw, const float* __restrict__ lb,
                         float* __restrict__ out){
    __shared__ int sc1, sc2;
    __shared__ float s0[3*DD], s1[3*DD];
    int t = threadIdx.x;   // 256
    if (t == 0){ sc1 = 0; sc2 = 0; }
    __syncthreads();
    int c1 = 0, c2 = 0;
    for (int i=t; i<NN; i+=256){ c1 += g_nm1[i]; c2 += g_nm2[i]; }
    #pragma unroll
    for (int o=16;o;o>>=1){
        c1 += __shfl_xor_sync(0xffffffffu, c1, o);
        c2 += __shfl_xor_sync(0xffffffffu, c2, o);
    }
    if ((t & 31) == 0){ atomicAdd(&sc1, c1); atomicAdd(&sc2, c2); }
    __syncthreads();
    if (t < 3*DD){
        int k = t >> 6;
        float cnt = (k==0) ? (float)NN : fmaxf((float)(k==1 ? sc1 : sc2), 1.f);
        float p = g_pool[t] / cnt;
        s0[t] = p * lw[t*2 + 0];
        s1[t] = p * lw[t*2 + 1];
    }
    __syncthreads();
    if (t == 0){
        float a = 0.f, b = 0.f;
        for (int i=0;i<3*DD;i++){ a += s0[i]; b += s1[i]; }
        out[0] = a + lb[0];
        out[1] = b + lb[1];
    }
}

// ---------------- host launcher -----------------------------------------------
extern "C" void kernel_launch(void* const* d_in, const int* in_sizes, int n_in,
                              void* d_out, int out_size){
    const float* h    = (const float*)d_in[0];
    const float* A1   = (const float*)d_in[2];
    const float* A2   = (const float*)d_in[3];
    const float* Ww   = (const float*)d_in[4];
    const float* Wb   = (const float*)d_in[5];
    const float* fc0  = (const float*)d_in[6];
    const float* fc1  = (const float*)d_in[7];
    const float* fc2  = (const float*)d_in[8];
    const float* linw = (const float*)d_in[9];
    const float* linb = (const float*)d_in[10];
    const int*   src  = (const int*)d_in[11];
    const int*   dst  = (const int*)d_in[12];
    float* out = (float*)d_out;

    k_init   <<<64,   256>>>();
    k_hist   <<<1024, 256>>>(src, dst, A1, A2);   // + A1/A2 mask gather
    k_scan   <<<2,   1024>>>();
    k_scatter<<<1024, 256>>>(src, dst);
    k1       <<<1024, 256>>>(h, Ww, Wb, fc0);     // dedup + AH + Z + ft0
    k2       <<<1024, 256>>>(fc1, fc2);           // AZ1/AZ2 + ft1 + ft2
    k_attn   <<<512,  256>>>();
    k_nfinal <<<1,    256>>>(linw, linb, out);
    (void)in_sizes; (void)n_in; (void)out_size;
}

// round 8
// speedup vs baseline: 2.2584x; 1.0078x over previous
#include <cuda_runtime.h>
#include <math.h>
#include <float.h>

#define NN 8192
#define DD 64
#define EE 524288

// ---------------- static device scratch -------------------------------------
__device__ float g_Z  [NN*DD];
__device__ float g_ft0[NN*DD];
__device__ float g_ft1[NN*DD];
__device__ float g_ft2[NN*DD];
__device__ float g_w0 [EE];            // 1/multiplicity, src-CSR order
__device__ int   g_sent[EE];           // src-CSR entries: dst | m1<<14 | m2<<15
__device__ int   g_dent[EE];           // dst-CSR entries: src | m1<<14 | m2<<15
__device__ unsigned char g_bits[EE];   // per-edge motif bits (1|2)
__device__ int   g_hists[NN], g_histd[NN];
__device__ int   g_offs[NN+1], g_offd[NN+1];
__device__ int   g_curs[NN],  g_curd[NN];
__device__ int   g_nm1[NN], g_nm2[NN];
__device__ float g_pool[3*DD];

// ---------------- init -------------------------------------------------------
__global__ void k_init(){
    int i = blockIdx.x*blockDim.x + threadIdx.x;
    int T = gridDim.x*blockDim.x;
    for (int j=i; j<NN; j+=T){ g_hists[j]=0; g_histd[j]=0; g_nm1[j]=0; g_nm2[j]=0; }
    if (i < 3*DD) g_pool[i] = 0.f;
}

// ---------------- A1/A2 mask gather (runs on side stream) --------------------
__global__ void k_bits(const int* __restrict__ src, const int* __restrict__ dst,
                       const float* __restrict__ A1, const float* __restrict__ A2){
    int e2 = blockIdx.x*blockDim.x + threadIdx.x;   // edges 2e2, 2e2+1
    if (e2 >= EE/2) return;
    int2 s = ((const int2*)src)[e2];
    int2 d = ((const int2*)dst)[e2];
    size_t ix = (size_t)s.x*NN + d.x;
    size_t iy = (size_t)s.y*NN + d.y;
    float a1x = __ldcs(&A1[ix]);
    float a2x = __ldcs(&A2[ix]);
    float a1y = __ldcs(&A1[iy]);
    float a2y = __ldcs(&A2[iy]);
    uchar2 b;
    b.x = (unsigned char)(((a1x > 0.f) ? 1 : 0) | ((a2x > 0.f) ? 2 : 0));
    b.y = (unsigned char)(((a1y > 0.f) ? 1 : 0) | ((a2y > 0.f) ? 2 : 0));
    ((uchar2*)g_bits)[e2] = b;
}

// ---------------- hist (counts only) ------------------------------------------
__global__ void k_hist(const int* __restrict__ src, const int* __restrict__ dst){
    int e2 = blockIdx.x*blockDim.x + threadIdx.x;
    if (e2 >= EE/2) return;
    int2 s = ((const int2*)src)[e2];
    int2 d = ((const int2*)dst)[e2];
    atomicAdd(&g_hists[s.x], 1); atomicAdd(&g_hists[s.y], 1);
    atomicAdd(&g_histd[d.x], 1); atomicAdd(&g_histd[d.y], 1);
}

__global__ void k_scan(){  // blockIdx 0 -> src CSR, 1 -> dst CSR
    int* hist = blockIdx.x ? g_histd : g_hists;
    int* off  = blockIdx.x ? g_offd  : g_offs;
    int* cur  = blockIdx.x ? g_curd  : g_curs;
    __shared__ int s[1024];
    int t = threadIdx.x;
    int base = t*8;
    int loc[8]; int sum = 0;
    #pragma unroll
    for (int i=0;i<8;i++){ loc[i]=sum; sum += hist[base+i]; }
    s[t] = sum;
    __syncthreads();
    for (int off2=1; off2<1024; off2<<=1){
        int v = (t>=off2) ? s[t-off2] : 0;
        __syncthreads();
        s[t] += v;
        __syncthreads();
    }
    int ex = (t==0) ? 0 : s[t-1];
    #pragma unroll
    for (int i=0;i<8;i++){ int o = ex + loc[i]; off[base+i]=o; cur[base+i]=o; }
    if (t == 1023) off[NN] = ex + sum;
}

// scatter: atomics + stores (bits already in g_bits)
__global__ void k_scatter(const int* __restrict__ src, const int* __restrict__ dst){
    int e2 = blockIdx.x*blockDim.x + threadIdx.x;
    if (e2 >= EE/2) return;
    int2 s = ((const int2*)src)[e2];
    int2 d = ((const int2*)dst)[e2];
    uchar2 b = ((const uchar2*)g_bits)[e2];
    int bx = ((int)b.x) << 14;
    int by = ((int)b.y) << 14;
    g_sent[atomicAdd(&g_curs[s.x], 1)] = d.x | bx;
    g_dent[atomicAdd(&g_curd[d.x], 1)] = s.x | bx;
    g_sent[atomicAdd(&g_curs[s.y], 1)] = d.y | by;
    g_dent[atomicAdd(&g_curd[d.y], 1)] = s.y | by;
}

// ---------------- k1: dedup weights + AH gather + Z = AH@Ww.T+Wb + ft0=Z@fc0 --
__global__ void k1(const float* __restrict__ h, const float* __restrict__ Ww,
                   const float* __restrict__ Wb, const float* __restrict__ fc0){
    __shared__ float sW[DD*DD];     // sW[k*64+j] = Ww[j][k]
    __shared__ float sF[DD*DD];     // fc0 natural layout [k][j]
    __shared__ int   sd [8*512];
    __shared__ float srow[8][DD];
    int t = threadIdx.x;            // 256
    for (int x=t; x<DD*DD; x+=256){
        int k = x >> 6, j = x & 63;
        sW[x] = Ww[j*DD + k];
        sF[x] = fc0[x];
    }
    __syncthreads();
    int wl   = t >> 5;
    int lane = t & 31;
    int row  = blockIdx.x*8 + wl;
    int lo = g_offs[row], hi = g_offs[row+1];
    int L = hi - lo;
    float ax=0.f, ay=0.f;
    int*   my = sd + wl*512;
    if (L <= 512){
        for (int i=lane; i<L; i+=32) my[i] = g_sent[lo+i];
        __syncwarp();
        for (int i=lane; i<L; i+=32){
            int dv = my[i] & 0x3FFF; int c = 0;
            for (int j=0;j<L;j++) c += ((my[j]&0x3FFF)==dv);
            g_w0[lo+i] = 1.f/(float)c;
        }
        __syncwarp();
        #pragma unroll 4
        for (int i=0; i<L; i++){
            float w0 = g_w0[lo+i];
            float2 v = ((const float2*)(h + (size_t)(my[i] & 0x3FFF)*DD))[lane];
            ax += w0*v.x; ay += w0*v.y;
        }
    } else {
        for (int i=lane; i<L; i+=32){
            int dv = g_sent[lo+i] & 0x3FFF; int c = 0;
            for (int j=0;j<L;j++) c += ((g_sent[lo+j]&0x3FFF)==dv);
            g_w0[lo+i] = 1.f/(float)c;
        }
        __syncwarp();
        for (int i=lo; i<hi; i++){
            float w0 = g_w0[i];
            float2 v = ((const float2*)(h + (size_t)(g_sent[i] & 0x3FFF)*DD))[lane];
            ax += w0*v.x; ay += w0*v.y;
        }
    }
    srow[wl][2*lane] = ax; srow[wl][2*lane+1] = ay;
    __syncwarp();
    float2 z = ((const float2*)Wb)[lane];
    #pragma unroll 8
    for (int k=0;k<DD;k++){
        float a = srow[wl][k];
        float2 wv = ((const float2*)(sW + k*DD))[lane];
        z.x += a*wv.x; z.y += a*wv.y;
    }
    ((float2*)(g_Z + (size_t)row*DD))[lane] = z;
    __syncwarp();
    srow[wl][2*lane] = z.x; srow[wl][2*lane+1] = z.y;
    __syncwarp();
    float2 f = make_float2(0.f, 0.f);
    #pragma unroll 8
    for (int k=0;k<DD;k++){
        float a = srow[wl][k];
        float2 wv = ((const float2*)(sF + k*DD))[lane];
        f.x += a*wv.x; f.y += a*wv.y;
    }
    ((float2*)(g_ft0 + (size_t)row*DD))[lane] = f;
}

// ---------------- k2: AZ1/AZ2 gather + ft1=AZ1@fc1, ft2=AZ2@fc2 --------------
__global__ void k2(const float* __restrict__ fc1, const float* __restrict__ fc2){
    __shared__ float sF1[DD*DD];
    __shared__ float sF2[DD*DD];
    __shared__ float srow[8][2*DD];
    int t = threadIdx.x;   // 256
    for (int x=t; x<DD*DD; x+=256){ sF1[x] = fc1[x]; sF2[x] = fc2[x]; }
    __syncthreads();
    int wl   = t >> 5;
    int lane = t & 31;
    int row  = blockIdx.x*8 + wl;
    int lo = g_offs[row], hi = g_offs[row+1];
    float a1x=0.f,a1y=0.f,a2x=0.f,a2y=0.f;
    #pragma unroll 4
    for (int i=lo; i<hi; i++){
        int w = g_sent[i];
        float w0 = g_w0[i];
        float w1 = (w & (1<<14)) ? w0 : 0.f;
        float w2 = (w & (1<<15)) ? w0 : 0.f;
        float2 v = ((const float2*)(g_Z + (size_t)(w & 0x3FFF)*DD))[lane];
        a1x += w1*v.x; a1y += w1*v.y;
        a2x += w2*v.x; a2y += w2*v.y;
    }
    srow[wl][2*lane]      = a1x; srow[wl][2*lane+1]      = a1y;
    srow[wl][DD+2*lane]   = a2x; srow[wl][DD+2*lane+1]   = a2y;
    __syncwarp();
    float2 f1 = make_float2(0.f,0.f), f2 = make_float2(0.f,0.f);
    #pragma unroll 8
    for (int k=0;k<DD;k++){
        float a1 = srow[wl][k];
        float a2 = srow[wl][DD+k];
        float2 w1 = ((const float2*)(sF1 + k*DD))[lane];
        float2 w2 = ((const float2*)(sF2 + k*DD))[lane];
        f1.x += a1*w1.x; f1.y += a1*w1.y;
        f2.x += a2*w2.x; f2.y += a2*w2.y;
    }
    ((float2*)(g_ft1 + (size_t)row*DD))[lane] = f1;
    ((float2*)(g_ft2 + (size_t)row*DD))[lane] = f2;
}

// ---------------- attention helpers ------------------------------------------
#define ONLINE_UPD4(m, den, acc, p, v) do {              \
    float _mn = fmaxf((m), (p));                         \
    float _sc = __expf((m) - _mn);                       \
    float _w  = __expf((p) - _mn);                       \
    (den) = (den)*_sc + _w;                              \
    (acc).x = (acc).x*_sc + _w*(v).x;                    \
    (acc).y = (acc).y*_sc + _w*(v).y;                    \
    (acc).z = (acc).z*_sc + _w*(v).z;                    \
    (acc).w = (acc).w*_sc + _w*(v).w;                    \
    (m) = _mn;                                           \
} while(0)

#define ONLINE_UPD4X2(m, den, acc, pa, va, pb, vb) do {  \
    float _mn = fmaxf((m), fmaxf((pa), (pb)));           \
    float _sc = __expf((m) - _mn);                       \
    float _wa = __expf((pa) - _mn);                      \
    float _wb = __expf((pb) - _mn);                      \
    (den) = (den)*_sc + _wa + _wb;                       \
    (acc).x = (acc).x*_sc + _wa*(va).x + _wb*(vb).x;     \
    (acc).y = (acc).y*_sc + _wa*(va).y + _wb*(vb).y;     \
    (acc).z = (acc).z*_sc + _wa*(va).z + _wb*(vb).z;     \
    (acc).w = (acc).w*_sc + _wa*(va).w + _wb*(vb).w;     \
    (m) = _mn;                                           \
} while(0)

__device__ __forceinline__ float red16(float p, unsigned gmask){
    #pragma unroll
    for (int o=8;o;o>>=1) p += __shfl_xor_sync(gmask, p, o);
    return p;
}
__device__ __forceinline__ float dot4(float4 a, float4 b){
    return a.x*b.x + a.y*b.y + a.z*b.z + a.w*b.w;
}

// ---------------- attn0: motif 0 only (runs ∥ with k2) -----------------------
__global__ void k_attn0(){
    __shared__ float sacc[DD];
    int t = threadIdx.x;
    if (t < DD) sacc[t] = 0.f;
    __syncthreads();
    int hl = t & 15;
    unsigned gmask = 0xFFFFu << (t & 16);
    int d  = (blockIdx.x*256 + t) >> 4;
    if (d < NN){
        int lo = g_offd[d], hi = g_offd[d+1];
        if (lo < hi){
            float4 f0 = ((const float4*)(g_ft0 + (size_t)d*DD))[hl];
            float m0=-FLT_MAX, den0=0.f; float4 a0 = make_float4(0,0,0,0);
            int i = lo;
            for (; i+1 < hi; i += 2){
                int sa = g_dent[i]   & 0x3FFF;
                int sb = g_dent[i+1] & 0x3FFF;
                float4 va = ((const float4*)(g_ft0 + (size_t)sa*DD))[hl];
                float4 vb = ((const float4*)(g_ft0 + (size_t)sb*DD))[hl];
                float pa = red16(dot4(va, f0), gmask) * 0.125f;
                float pb = red16(dot4(vb, f0), gmask) * 0.125f;
                ONLINE_UPD4X2(m0, den0, a0, pa, va, pb, vb);
            }
            if (i < hi){
                int s = g_dent[i] & 0x3FFF;
                float4 v0 = ((const float4*)(g_ft0 + (size_t)s*DD))[hl];
                float p0 = red16(dot4(v0, f0), gmask) * 0.125f;
                ONLINE_UPD4(m0, den0, a0, p0, v0);
            }
            float r0 = 1.f/fmaxf(den0, 1e-9f);
            atomicAdd(&sacc[4*hl+0], a0.x*r0); atomicAdd(&sacc[4*hl+1], a0.y*r0);
            atomicAdd(&sacc[4*hl+2], a0.z*r0); atomicAdd(&sacc[4*hl+3], a0.w*r0);
        }
    }
    __syncthreads();
    if (t < DD) atomicAdd(&g_pool[t], sacc[t]);
}

// ---------------- attn12: motifs 1 & 2 ---------------------------------------
__global__ void k_attn12(){
    __shared__ float sacc[2*DD];
    int t = threadIdx.x;
    for (int j=t; j<2*DD; j+=256) sacc[j] = 0.f;
    __syncthreads();
    int hl = t & 15;
    unsigned gmask = 0xFFFFu << (t & 16);
    int d  = (blockIdx.x*256 + t) >> 4;
    if (d < NN){
        int lo = g_offd[d], hi = g_offd[d+1];
        if (lo < hi){
            float4 f1 = ((const float4*)(g_ft1 + (size_t)d*DD))[hl];
            float4 f2 = ((const float4*)(g_ft2 + (size_t)d*DD))[hl];
            float m1=-FLT_MAX, den1=0.f; float4 a1 = make_float4(0,0,0,0);
            float m2=-FLT_MAX, den2=0.f; float4 a2 = make_float4(0,0,0,0);
            for (int i=lo; i<hi; i++){
                int w = g_dent[i];
                int s = w & 0x3FFF;
                if (w & (1<<14)){
                    float4 v1 = ((const float4*)(g_ft1 + (size_t)s*DD))[hl];
                    float p1 = red16(dot4(v1, f1), gmask) * 0.125f;
                    ONLINE_UPD4(m1, den1, a1, p1, v1);
                    if (hl == 0){ g_nm1[s] = 1; g_nm1[d] = 1; }
                }
                if (w & (1<<15)){
                    float4 v2 = ((const float4*)(g_ft2 + (size_t)s*DD))[hl];
                    float p2 = red16(dot4(v2, f2), gmask) * 0.125f;
                    ONLINE_UPD4(m2, den2, a2, p2, v2);
                    if (hl == 0){ g_nm2[s] = 1; g_nm2[d] = 1; }
                }
            }
            if (den1 > 0.f){
                float r1 = 1.f/den1;
                atomicAdd(&sacc[4*hl+0], a1.x*r1); atomicAdd(&sacc[4*hl+1], a1.y*r1);
                atomicAdd(&sacc[4*hl+2], a1.z*r1); atomicAdd(&sacc[4*hl+3], a1.w*r1);
            }
            if (den2 > 0.f){
                float r2 = 1.f/den2;
                atomicAdd(&sacc[DD+4*hl+0], a2.x*r2); atomicAdd(&sacc[DD+4*hl+1], a2.y*r2);
                atomicAdd(&sacc[DD+4*hl+2], a2.z*r2); atomicAdd(&sacc[DD+4*hl+3], a2.w*r2);
            }
        }
    }
    __syncthreads();
    for (int j=t; j<2*DD; j+=256) atomicAdd(&g_pool[DD+j], sacc[j]);
}

// ---------------- node counts + final linear (fused, one block) --------------
__global__ void k_nfinal(const float* __restrict__ lw, const float* __restrict__ lb,
                         float* __restrict__ out){
    __shared__ int sc1, sc2;
    __shared__ float s0[3*DD], s1[3*DD];
    int t = threadIdx.x;   // 256
    if (t == 0){ sc1 = 0; sc2 = 0; }
    __syncthreads();
    int c1 = 0, c2 = 0;
    for (int i=t; i<NN; i+=256){ c1 += g_nm1[i]; c2 += g_nm2[i]; }
    #pragma unroll
    for (int o=16;o;o>>=1){
        c1 += __shfl_xor_sync(0xffffffffu, c1, o);
        c2 += __shfl_xor_sync(0xffffffffu, c2, o);
    }
    if ((t & 31) == 0){ atomicAdd(&sc1, c1); atomicAdd(&sc2, c2); }
    __syncthreads();
    if (t < 3*DD){
        int k = t >> 6;
        float cnt = (k==0) ? (float)NN : fmaxf((float)(k==1 ? sc1 : sc2), 1.f);
        float p = g_pool[t] / cnt;
        s0[t] = p * lw[t*2 + 0];
        s1[t] = p * lw[t*2 + 1];
    }
    __syncthreads();
    if (t == 0){
        float a = 0.f, b = 0.f;
        for (int i=0;i<3*DD;i++){ a += s0[i]; b += s1[i]; }
        out[0] = a + lb[0];
        out[1] = b + lb[1];
    }
}

// ---------------- host launcher -----------------------------------------------
// side stream + events created once (host-side resources; identical captured
// work on every call — the graph itself is deterministic)
static cudaStream_t get_s1(){
    static cudaStream_t s = nullptr;
    if (!s) cudaStreamCreateWithFlags(&s, cudaStreamNonBlocking);
    return s;
}
static cudaEvent_t get_ev(int i){
    static cudaEvent_t e[4] = {nullptr,nullptr,nullptr,nullptr};
    if (!e[i]) cudaEventCreateWithFlags(&e[i], cudaEventDisableTiming);
    return e[i];
}

extern "C" void kernel_launch(void* const* d_in, const int* in_sizes, int n_in,
                              void* d_out, int out_size){
    const float* h    = (const float*)d_in[0];
    const float* A1   = (const float*)d_in[2];
    const float* A2   = (const float*)d_in[3];
    const float* Ww   = (const float*)d_in[4];
    const float* Wb   = (const float*)d_in[5];
    const float* fc0  = (const float*)d_in[6];
    const float* fc1  = (const float*)d_in[7];
    const float* fc2  = (const float*)d_in[8];
    const float* linw = (const float*)d_in[9];
    const float* linb = (const float*)d_in[10];
    const int*   src  = (const int*)d_in[11];
    const int*   dst  = (const int*)d_in[12];
    float* out = (float*)d_out;

    cudaStream_t s1 = get_s1();
    cudaEvent_t evFork  = get_ev(0);
    cudaEvent_t evBits  = get_ev(1);
    cudaEvent_t evFt0   = get_ev(2);
    cudaEvent_t evAttn0 = get_ev(3);

    // fork: bits gather on s1, overlapping init+hist+scan on main stream
    cudaEventRecord(evFork, 0);
    cudaStreamWaitEvent(s1, evFork, 0);
    k_bits   <<<1024, 256, 0, s1>>>(src, dst, A1, A2);
    cudaEventRecord(evBits, s1);

    k_init   <<<64,   256>>>();
    k_hist   <<<1024, 256>>>(src, dst);
    k_scan   <<<2,   1024>>>();

    // join: scatter needs bits
    cudaStreamWaitEvent(0, evBits, 0);
    k_scatter<<<1024, 256>>>(src, dst);
    k1       <<<1024, 256>>>(h, Ww, Wb, fc0);       // dedup + AH + Z + ft0

    // fork: attn0 (needs ft0 + dst-CSR) ∥ k2 (needs Z + w0)
    cudaEventRecord(evFt0, 0);
    cudaStreamWaitEvent(s1, evFt0, 0);
    k_attn0  <<<512,  256, 0, s1>>>();
    cudaEventRecord(evAttn0, s1);

    k2       <<<1024, 256>>>(fc1, fc2);             // AZ1/AZ2 + ft1 + ft2
    k_attn12 <<<512,  256>>>();

    // join before final
    cudaStreamWaitEvent(0, evAttn0, 0);
    k_nfinal <<<1,    256>>>(linw, linb, out);
    (void)in_sizes; (void)n_in; (void)out_size;
}

// round 9
// speedup vs baseline: 2.3219x; 1.0281x over previous
#include <cuda_runtime.h>
#include <math.h>
#include <float.h>

#define NN 8192
#define DD 64
#define EE 524288

// ---------------- static device scratch -------------------------------------
__device__ __align__(16) float g_Z  [NN*DD];
__device__ __align__(16) float g_ft0[NN*DD];
__device__ __align__(16) float g_ft1[NN*DD];
__device__ __align__(16) float g_ft2[NN*DD];
__device__ __align__(16) float g_w0 [EE];
__device__ __align__(16) int   g_sent[EE];     // dst | m1<<14 | m2<<15 (src-CSR)
__device__ __align__(16) int   g_dent[EE];     // src | m1<<14 | m2<<15 (dst-CSR)
__device__ __align__(16) unsigned char g_bits[EE];
__device__ __align__(16) int   g_hists[NN];
__device__ __align__(16) int   g_histd[NN];
__device__ __align__(16) int   g_offs[NN+8];
__device__ __align__(16) int   g_offd[NN+8];
__device__ __align__(16) int   g_curs[NN];
__device__ __align__(16) int   g_curd[NN];
__device__ int   g_nm1[NN], g_nm2[NN];
__device__ float g_pool[3*DD];

// ---------------- init -------------------------------------------------------
__global__ void k_init(){
    int i = blockIdx.x*blockDim.x + threadIdx.x;
    int T = gridDim.x*blockDim.x;
    for (int j=i; j<NN; j+=T){ g_hists[j]=0; g_histd[j]=0; g_nm1[j]=0; g_nm2[j]=0; }
    if (i < 3*DD) g_pool[i] = 0.f;
}

// ---------------- A1/A2 mask gather (side stream) ----------------------------
__global__ void k_bits(const int* __restrict__ src, const int* __restrict__ dst,
                       const float* __restrict__ A1, const float* __restrict__ A2){
    int e2 = blockIdx.x*blockDim.x + threadIdx.x;
    if (e2 >= EE/2) return;
    int2 s = ((const int2*)src)[e2];
    int2 d = ((const int2*)dst)[e2];
    size_t ix = (size_t)s.x*NN + d.x;
    size_t iy = (size_t)s.y*NN + d.y;
    float a1x = __ldcs(&A1[ix]);
    float a2x = __ldcs(&A2[ix]);
    float a1y = __ldcs(&A1[iy]);
    float a2y = __ldcs(&A2[iy]);
    uchar2 b;
    b.x = (unsigned char)(((a1x > 0.f) ? 1 : 0) | ((a2x > 0.f) ? 2 : 0));
    b.y = (unsigned char)(((a1y > 0.f) ? 1 : 0) | ((a2y > 0.f) ? 2 : 0));
    ((uchar2*)g_bits)[e2] = b;
}

// ---------------- hist (counts only) ------------------------------------------
__global__ void k_hist(const int* __restrict__ src, const int* __restrict__ dst){
    int e2 = blockIdx.x*blockDim.x + threadIdx.x;
    if (e2 >= EE/2) return;
    int2 s = ((const int2*)src)[e2];
    int2 d = ((const int2*)dst)[e2];
    atomicAdd(&g_hists[s.x], 1); atomicAdd(&g_hists[s.y], 1);
    atomicAdd(&g_histd[d.x], 1); atomicAdd(&g_histd[d.y], 1);
}

// ---------------- fast scan: local-8 + warp shfl + 32-partials (2 barriers) ---
__global__ void k_scan(){
    int* hist = blockIdx.x ? g_histd : g_hists;
    int* off  = blockIdx.x ? g_offd  : g_offs;
    int* cur  = blockIdx.x ? g_curd  : g_curs;
    __shared__ int wsum[32];
    int t = threadIdx.x;         // 1024
    int lane = t & 31, wid = t >> 5;
    int4 a = ((const int4*)hist)[2*t];
    int4 b = ((const int4*)hist)[2*t+1];
    int l0=a.x, l1=l0+a.y, l2=l1+a.z, l3=l2+a.w;
    int l4=l3+b.x, l5=l4+b.y, l6=l5+b.z, l7=l6+b.w;
    int tot = l7;
    int pre = tot;
    #pragma unroll
    for (int o=1;o<32;o<<=1){ int v=__shfl_up_sync(0xffffffffu, pre, o); if (lane>=o) pre += v; }
    int wex = pre - tot;                 // exclusive within warp
    if (lane == 31) wsum[wid] = pre;     // warp total (inclusive of last)
    __syncthreads();
    if (wid == 0){
        int v = wsum[lane];
        int p = v;
        #pragma unroll
        for (int o=1;o<32;o<<=1){ int u=__shfl_up_sync(0xffffffffu, p, o); if (lane>=o) p += u; }
        wsum[lane] = p - v;              // exclusive warp offsets
    }
    __syncthreads();
    int base = wsum[wid] + wex;
    int4 o0 = make_int4(base,    base+l0, base+l1, base+l2);
    int4 o1 = make_int4(base+l3, base+l4, base+l5, base+l6);
    ((int4*)off)[2*t]   = o0;  ((int4*)off)[2*t+1] = o1;
    ((int4*)cur)[2*t]   = o0;  ((int4*)cur)[2*t+1] = o1;
    if (t == 1023) off[NN] = base + l7;
}

// ---------------- scatter halves (independent atomic chains) ------------------
__global__ void k_scat_s(const int* __restrict__ src, const int* __restrict__ dst){
    int e2 = blockIdx.x*blockDim.x + threadIdx.x;
    if (e2 >= EE/2) return;
    int2 s = ((const int2*)src)[e2];
    int2 d = ((const int2*)dst)[e2];
    uchar2 b = ((const uchar2*)g_bits)[e2];
    g_sent[atomicAdd(&g_curs[s.x], 1)] = d.x | (((int)b.x) << 14);
    g_sent[atomicAdd(&g_curs[s.y], 1)] = d.y | (((int)b.y) << 14);
}
__global__ void k_scat_d(const int* __restrict__ src, const int* __restrict__ dst){
    int e2 = blockIdx.x*blockDim.x + threadIdx.x;
    if (e2 >= EE/2) return;
    int2 s = ((const int2*)src)[e2];
    int2 d = ((const int2*)dst)[e2];
    uchar2 b = ((const uchar2*)g_bits)[e2];
    g_dent[atomicAdd(&g_curd[d.x], 1)] = s.x | (((int)b.x) << 14);
    g_dent[atomicAdd(&g_curd[d.y], 1)] = s.y | (((int)b.y) << 14);
}

// ---------------- k1: dedup weights + AH gather + Z + ft0 --------------------
__global__ void k1(const float* __restrict__ h, const float* __restrict__ Ww,
                   const float* __restrict__ Wb, const float* __restrict__ fc0){
    __shared__ float sW[DD*DD];     // sW[k*64+j] = Ww[j][k]
    __shared__ float sF[DD*DD];     // fc0 natural [k][j]
    __shared__ int   sd [8*512];
    __shared__ float srow[8][DD];
    int t = threadIdx.x;            // 256
    for (int x=t; x<DD*DD; x+=256){
        int k = x >> 6, j = x & 63;
        sW[x] = Ww[j*DD + k];
        sF[x] = fc0[x];
    }
    __syncthreads();
    int wl   = t >> 5;
    int lane = t & 31;
    int row  = blockIdx.x*8 + wl;
    int lo = g_offs[row], hi = g_offs[row+1];
    int L = hi - lo;
    float ax=0.f, ay=0.f;
    int*   my = sd + wl*512;
    if (L <= 512){
        for (int i=lane; i<L; i+=32) my[i] = g_sent[lo+i];
        __syncwarp();
        for (int i=lane; i<L; i+=32){
            int dv = my[i] & 0x3FFF; int c = 0;
            for (int j=0;j<L;j++) c += ((my[j]&0x3FFF)==dv);
            g_w0[lo+i] = 1.f/(float)c;
        }
        __syncwarp();
        #pragma unroll 4
        for (int i=0; i<L; i++){
            float w0 = g_w0[lo+i];
            float2 v = ((const float2*)(h + (size_t)(my[i] & 0x3FFF)*DD))[lane];
            ax += w0*v.x; ay += w0*v.y;
        }
    } else {
        for (int i=lane; i<L; i+=32){
            int dv = g_sent[lo+i] & 0x3FFF; int c = 0;
            for (int j=0;j<L;j++) c += ((g_sent[lo+j]&0x3FFF)==dv);
            g_w0[lo+i] = 1.f/(float)c;
        }
        __syncwarp();
        for (int i=lo; i<hi; i++){
            float w0 = g_w0[i];
            float2 v = ((const float2*)(h + (size_t)(g_sent[i] & 0x3FFF)*DD))[lane];
            ax += w0*v.x; ay += w0*v.y;
        }
    }
    srow[wl][2*lane] = ax; srow[wl][2*lane+1] = ay;
    __syncwarp();
    float2 z = ((const float2*)Wb)[lane];
    #pragma unroll 8
    for (int k=0;k<DD;k++){
        float a = srow[wl][k];
        float2 wv = ((const float2*)(sW + k*DD))[lane];
        z.x += a*wv.x; z.y += a*wv.y;
    }
    ((float2*)(g_Z + (size_t)row*DD))[lane] = z;
    __syncwarp();
    srow[wl][2*lane] = z.x; srow[wl][2*lane+1] = z.y;
    __syncwarp();
    float2 f = make_float2(0.f, 0.f);
    #pragma unroll 8
    for (int k=0;k<DD;k++){
        float a = srow[wl][k];
        float2 wv = ((const float2*)(sF + k*DD))[lane];
        f.x += a*wv.x; f.y += a*wv.y;
    }
    ((float2*)(g_ft0 + (size_t)row*DD))[lane] = f;
}

// ---------------- k2: AZ1/AZ2 gather + ft1/ft2 (2 rows per warp) --------------
__global__ void k2(const float* __restrict__ fc1, const float* __restrict__ fc2){
    __shared__ float sF1[DD*DD];
    __shared__ float sF2[DD*DD];
    __shared__ float srow[16][2*DD];
    int t = threadIdx.x;   // 256
    for (int x=t; x<DD*DD; x+=256){ sF1[x] = fc1[x]; sF2[x] = fc2[x]; }
    __syncthreads();
    int g  = t >> 4;                      // 16-lane group id (0..15)
    int hl = t & 15;
    unsigned gmask = 0xFFFFu << (t & 16);
    int row = blockIdx.x*16 + g;
    int lo = g_offs[row], hi = g_offs[row+1];
    float4 acc1 = make_float4(0,0,0,0), acc2 = make_float4(0,0,0,0);
    #pragma unroll 4
    for (int i=lo; i<hi; i++){
        int w = g_sent[i];
        float w0 = g_w0[i];
        float w1 = (w & (1<<14)) ? w0 : 0.f;
        float w2 = (w & (1<<15)) ? w0 : 0.f;
        float4 v = ((const float4*)(g_Z + (size_t)(w & 0x3FFF)*DD))[hl];
        acc1.x += w1*v.x; acc1.y += w1*v.y; acc1.z += w1*v.z; acc1.w += w1*v.w;
        acc2.x += w2*v.x; acc2.y += w2*v.y; acc2.z += w2*v.z; acc2.w += w2*v.w;
    }
    ((float4*)&srow[g][0])[hl]  = acc1;
    ((float4*)&srow[g][DD])[hl] = acc2;
    __syncwarp(gmask);
    float4 f1 = make_float4(0,0,0,0), f2 = make_float4(0,0,0,0);
    #pragma unroll 8
    for (int k=0;k<DD;k++){
        float a1 = srow[g][k];
        float a2 = srow[g][DD+k];
        float4 w1 = ((const float4*)(sF1 + k*DD))[hl];
        float4 w2 = ((const float4*)(sF2 + k*DD))[hl];
        f1.x += a1*w1.x; f1.y += a1*w1.y; f1.z += a1*w1.z; f1.w += a1*w1.w;
        f2.x += a2*w2.x; f2.y += a2*w2.y; f2.z += a2*w2.z; f2.w += a2*w2.w;
    }
    ((float4*)(g_ft1 + (size_t)row*DD))[hl] = f1;
    ((float4*)(g_ft2 + (size_t)row*DD))[hl] = f2;
}

// ---------------- attention helpers ------------------------------------------
#define ONLINE_UPD4(m, den, acc, p, v) do {              \
    float _mn = fmaxf((m), (p));                         \
    float _sc = __expf((m) - _mn);                       \
    float _w  = __expf((p) - _mn);                       \
    (den) = (den)*_sc + _w;                              \
    (acc).x = (acc).x*_sc + _w*(v).x;                    \
    (acc).y = (acc).y*_sc + _w*(v).y;                    \
    (acc).z = (acc).z*_sc + _w*(v).z;                    \
    (acc).w = (acc).w*_sc + _w*(v).w;                    \
    (m) = _mn;                                           \
} while(0)

#define ONLINE_UPD4X2(m, den, acc, pa, va, pb, vb) do {  \
    float _mn = fmaxf((m), fmaxf((pa), (pb)));           \
    float _sc = __expf((m) - _mn);                       \
    float _wa = __expf((pa) - _mn);                      \
    float _wb = __expf((pb) - _mn);                      \
    (den) = (den)*_sc + _wa + _wb;                       \
    (acc).x = (acc).x*_sc + _wa*(va).x + _wb*(vb).x;     \
    (acc).y = (acc).y*_sc + _wa*(va).y + _wb*(vb).y;     \
    (acc).z = (acc).z*_sc + _wa*(va).z + _wb*(vb).z;     \
    (acc).w = (acc).w*_sc + _wa*(va).w + _wb*(vb).w;     \
    (m) = _mn;                                           \
} while(0)

__device__ __forceinline__ float red16(float p, unsigned gmask){
    #pragma unroll
    for (int o=8;o;o>>=1) p += __shfl_xor_sync(gmask, p, o);
    return p;
}
__device__ __forceinline__ float dot4(float4 a, float4 b){
    return a.x*b.x + a.y*b.y + a.z*b.z + a.w*b.w;
}

// ---------------- attn0: motif 0 (∥ with k2) ---------------------------------
__global__ void k_attn0(){
    __shared__ float sacc[DD];
    int t = threadIdx.x;
    if (t < DD) sacc[t] = 0.f;
    __syncthreads();
    int hl = t & 15;
    unsigned gmask = 0xFFFFu << (t & 16);
    int d  = (blockIdx.x*256 + t) >> 4;
    if (d < NN){
        int lo = g_offd[d], hi = g_offd[d+1];
        if (lo < hi){
            float4 f0 = ((const float4*)(g_ft0 + (size_t)d*DD))[hl];
            float m0=-FLT_MAX, den0=0.f; float4 a0 = make_float4(0,0,0,0);
            int i = lo;
            for (; i+1 < hi; i += 2){
                int sa = g_dent[i]   & 0x3FFF;
                int sb = g_dent[i+1] & 0x3FFF;
                float4 va = ((const float4*)(g_ft0 + (size_t)sa*DD))[hl];
                float4 vb = ((const float4*)(g_ft0 + (size_t)sb*DD))[hl];
                float pa = red16(dot4(va, f0), gmask) * 0.125f;
                float pb = red16(dot4(vb, f0), gmask) * 0.125f;
                ONLINE_UPD4X2(m0, den0, a0, pa, va, pb, vb);
            }
            if (i < hi){
                int s = g_dent[i] & 0x3FFF;
                float4 v0 = ((const float4*)(g_ft0 + (size_t)s*DD))[hl];
                float p0 = red16(dot4(v0, f0), gmask) * 0.125f;
                ONLINE_UPD4(m0, den0, a0, p0, v0);
            }
            float r0 = 1.f/fmaxf(den0, 1e-9f);
            atomicAdd(&sacc[4*hl+0], a0.x*r0); atomicAdd(&sacc[4*hl+1], a0.y*r0);
            atomicAdd(&sacc[4*hl+2], a0.z*r0); atomicAdd(&sacc[4*hl+3], a0.w*r0);
        }
    }
    __syncthreads();
    if (t < DD) atomicAdd(&g_pool[t], sacc[t]);
}

// ---------------- attn12: motifs 1 & 2 ---------------------------------------
__global__ void k_attn12(){
    __shared__ float sacc[2*DD];
    int t = threadIdx.x;
    for (int j=t; j<2*DD; j+=256) sacc[j] = 0.f;
    __syncthreads();
    int hl = t & 15;
    unsigned gmask = 0xFFFFu << (t & 16);
    int d  = (blockIdx.x*256 + t) >> 4;
    if (d < NN){
        int lo = g_offd[d], hi = g_offd[d+1];
        if (lo < hi){
            float4 f1 = ((const float4*)(g_ft1 + (size_t)d*DD))[hl];
            float4 f2 = ((const float4*)(g_ft2 + (size_t)d*DD))[hl];
            float m1=-FLT_MAX, den1=0.f; float4 a1 = make_float4(0,0,0,0);
            float m2=-FLT_MAX, den2=0.f; float4 a2 = make_float4(0,0,0,0);
            for (int i=lo; i<hi; i++){
                int w = g_dent[i];
                int s = w & 0x3FFF;
                if (w & (1<<14)){
                    float4 v1 = ((const float4*)(g_ft1 + (size_t)s*DD))[hl];
                    float p1 = red16(dot4(v1, f1), gmask) * 0.125f;
                    ONLINE_UPD4(m1, den1, a1, p1, v1);
                    if (hl == 0){ g_nm1[s] = 1; g_nm1[d] = 1; }
                }
                if (w & (1<<15)){
                    float4 v2 = ((const float4*)(g_ft2 + (size_t)s*DD))[hl];
                    float p2 = red16(dot4(v2, f2), gmask) * 0.125f;
                    ONLINE_UPD4(m2, den2, a2, p2, v2);
                    if (hl == 0){ g_nm2[s] = 1; g_nm2[d] = 1; }
                }
            }
            if (den1 > 0.f){
                float r1 = 1.f/den1;
                atomicAdd(&sacc[4*hl+0], a1.x*r1); atomicAdd(&sacc[4*hl+1], a1.y*r1);
                atomicAdd(&sacc[4*hl+2], a1.z*r1); atomicAdd(&sacc[4*hl+3], a1.w*r1);
            }
            if (den2 > 0.f){
                float r2 = 1.f/den2;
                atomicAdd(&sacc[DD+4*hl+0], a2.x*r2); atomicAdd(&sacc[DD+4*hl+1], a2.y*r2);
                atomicAdd(&sacc[DD+4*hl+2], a2.z*r2); atomicAdd(&sacc[DD+4*hl+3], a2.w*r2);
            }
        }
    }
    __syncthreads();
    for (int j=t; j<2*DD; j+=256) atomicAdd(&g_pool[DD+j], sacc[j]);
}

// ---------------- node counts + final linear ----------------------------------
__global__ void k_nfinal(const float* __restrict__ lw, const float* __restrict__ lb,
                         float* __restrict__ out){
    __shared__ int sc1, sc2;
    __shared__ float s0[3*DD], s1[3*DD];
    int t = threadIdx.x;   // 256
    if (t == 0){ sc1 = 0; sc2 = 0; }
    __syncthreads();
    int c1 = 0, c2 = 0;
    for (int i=t; i<NN; i+=256){ c1 += g_nm1[i]; c2 += g_nm2[i]; }
    #pragma unroll
    for (int o=16;o;o>>=1){
        c1 += __shfl_xor_sync(0xffffffffu, c1, o);
        c2 += __shfl_xor_sync(0xffffffffu, c2, o);
    }
    if ((t & 31) == 0){ atomicAdd(&sc1, c1); atomicAdd(&sc2, c2); }
    __syncthreads();
    if (t < 3*DD){
        int k = t >> 6;
        float cnt = (k==0) ? (float)NN : fmaxf((float)(k==1 ? sc1 : sc2), 1.f);
        float p = g_pool[t] / cnt;
        s0[t] = p * lw[t*2 + 0];
        s1[t] = p * lw[t*2 + 1];
    }
    __syncthreads();
    if (t == 0){
        float a = 0.f, b = 0.f;
        for (int i=0;i<3*DD;i++){ a += s0[i]; b += s1[i]; }
        out[0] = a + lb[0];
        out[1] = b + lb[1];
    }
}

// ---------------- host launcher -----------------------------------------------
static cudaStream_t get_s1(){
    static cudaStream_t s = nullptr;
    if (!s) cudaStreamCreateWithFlags(&s, cudaStreamNonBlocking);
    return s;
}
static cudaEvent_t get_ev(int i){
    static cudaEvent_t e[6] = {};
    if (!e[i]) cudaEventCreateWithFlags(&e[i], cudaEventDisableTiming);
    return e[i];
}

extern "C" void kernel_launch(void* const* d_in, const int* in_sizes, int n_in,
                              void* d_out, int out_size){
    const float* h    = (const float*)d_in[0];
    const float* A1   = (const float*)d_in[2];
    const float* A2   = (const float*)d_in[3];
    const float* Ww   = (const float*)d_in[4];
    const float* Wb   = (const float*)d_in[5];
    const float* fc0  = (const float*)d_in[6];
    const float* fc1  = (const float*)d_in[7];
    const float* fc2  = (const float*)d_in[8];
    const float* linw = (const float*)d_in[9];
    const float* linb = (const float*)d_in[10];
    const int*   src  = (const int*)d_in[11];
    const int*   dst  = (const int*)d_in[12];
    float* out = (float*)d_out;

    cudaStream_t s1 = get_s1();
    cudaEvent_t evFork  = get_ev(0);
    cudaEvent_t evBits  = get_ev(1);
    cudaEvent_t evScan  = get_ev(2);
    cudaEvent_t evDent  = get_ev(3);
    cudaEvent_t evFt0   = get_ev(4);
    cudaEvent_t evAttn0 = get_ev(5);

    // fork: bits gather on s1 ∥ init+hist+scan on main stream
    cudaEventRecord(evFork, 0);
    cudaStreamWaitEvent(s1, evFork, 0);
    k_bits   <<<1024, 256, 0, s1>>>(src, dst, A1, A2);
    cudaEventRecord(evBits, s1);

    k_init   <<<64,   256>>>();
    k_hist   <<<1024, 256>>>(src, dst);
    k_scan   <<<2,   1024>>>();
    cudaEventRecord(evScan, 0);

    // dent scatter on s1 (after bits; needs scan)
    cudaStreamWaitEvent(s1, evScan, 0);
    k_scat_d <<<1024, 256, 0, s1>>>(src, dst);
    cudaEventRecord(evDent, s1);

    // sent scatter + k1 on main (needs bits)
    cudaStreamWaitEvent(0, evBits, 0);
    k_scat_s <<<1024, 256>>>(src, dst);
    k1       <<<1024, 256>>>(h, Ww, Wb, fc0);
    cudaEventRecord(evFt0, 0);

    // attn0 on s1 (after dent in s1 order; needs ft0)
    cudaStreamWaitEvent(s1, evFt0, 0);
    k_attn0  <<<512,  256, 0, s1>>>();
    cudaEventRecord(evAttn0, s1);

    k2       <<<512,  256>>>(fc1, fc2);
    cudaStreamWaitEvent(0, evDent, 0);
    k_attn12 <<<512,  256>>>();
    cudaStreamWaitEvent(0, evAttn0, 0);
    k_nfinal <<<1,    256>>>(linw, linb, out);
    (void)in_sizes; (void)n_in; (void)out_size;
}

// round 10
// speedup vs baseline: 2.3226x; 1.0003x over previous
#include <cuda_runtime.h>
#include <math.h>
#include <float.h>

#define NN 8192
#define DD 64
#define EE 524288

// ---------------- static device scratch -------------------------------------
__device__ __align__(16) float g_Z  [NN*DD];
__device__ __align__(16) float g_ft0[NN*DD];
__device__ __align__(16) float g_ft1[NN*DD];
__device__ __align__(16) float g_ft2[NN*DD];
__device__ __align__(16) float g_w0 [EE];
__device__ __align__(16) int   g_sent[EE];     // dst | m1<<14 | m2<<15 (src-CSR)
__device__ __align__(16) int   g_dent[EE];     // src | m1<<14 | m2<<15 (dst-CSR)
__device__ __align__(16) unsigned char g_bits[EE];
__device__ __align__(16) int   g_hists[NN];
__device__ __align__(16) int   g_histd[NN];
__device__ __align__(16) int   g_offs[NN+8];
__device__ __align__(16) int   g_offd[NN+8];
__device__ __align__(16) int   g_curs[NN];
__device__ __align__(16) int   g_curd[NN];
__device__ int   g_nm1[NN], g_nm2[NN];
__device__ float g_pool[3*DD];

// ---------------- init -------------------------------------------------------
__global__ void k_init(){
    int i = blockIdx.x*blockDim.x + threadIdx.x;
    int T = gridDim.x*blockDim.x;
    for (int j=i; j<NN; j+=T){ g_hists[j]=0; g_histd[j]=0; g_nm1[j]=0; g_nm2[j]=0; }
    if (i < 3*DD) g_pool[i] = 0.f;
}

// ---------------- A1/A2 mask gather: 4 edges/thread (8 outstanding probes) ---
__global__ void k_bits(const int* __restrict__ src, const int* __restrict__ dst,
                       const float* __restrict__ A1, const float* __restrict__ A2){
    int e4 = blockIdx.x*blockDim.x + threadIdx.x;
    if (e4 >= EE/4) return;
    int4 s = ((const int4*)src)[e4];
    int4 d = ((const int4*)dst)[e4];
    float a1x = __ldcs(&A1[(size_t)s.x*NN + d.x]);
    float a1y = __ldcs(&A1[(size_t)s.y*NN + d.y]);
    float a1z = __ldcs(&A1[(size_t)s.z*NN + d.z]);
    float a1w = __ldcs(&A1[(size_t)s.w*NN + d.w]);
    float a2x = __ldcs(&A2[(size_t)s.x*NN + d.x]);
    float a2y = __ldcs(&A2[(size_t)s.y*NN + d.y]);
    float a2z = __ldcs(&A2[(size_t)s.z*NN + d.z]);
    float a2w = __ldcs(&A2[(size_t)s.w*NN + d.w]);
    uchar4 b;
    b.x = (unsigned char)(((a1x > 0.f) ? 1 : 0) | ((a2x > 0.f) ? 2 : 0));
    b.y = (unsigned char)(((a1y > 0.f) ? 1 : 0) | ((a2y > 0.f) ? 2 : 0));
    b.z = (unsigned char)(((a1z > 0.f) ? 1 : 0) | ((a2z > 0.f) ? 2 : 0));
    b.w = (unsigned char)(((a1w > 0.f) ? 1 : 0) | ((a2w > 0.f) ? 2 : 0));
    ((uchar4*)g_bits)[e4] = b;
}

// ---------------- hist: 4 edges/thread ----------------------------------------
__global__ void k_hist(const int* __restrict__ src, const int* __restrict__ dst){
    int e4 = blockIdx.x*blockDim.x + threadIdx.x;
    if (e4 >= EE/4) return;
    int4 s = ((const int4*)src)[e4];
    int4 d = ((const int4*)dst)[e4];
    atomicAdd(&g_hists[s.x], 1); atomicAdd(&g_hists[s.y], 1);
    atomicAdd(&g_hists[s.z], 1); atomicAdd(&g_hists[s.w], 1);
    atomicAdd(&g_histd[d.x], 1); atomicAdd(&g_histd[d.y], 1);
    atomicAdd(&g_histd[d.z], 1); atomicAdd(&g_histd[d.w], 1);
}

// ---------------- fast scan (2 barriers) --------------------------------------
__global__ void k_scan(){
    int* hist = blockIdx.x ? g_histd : g_hists;
    int* off  = blockIdx.x ? g_offd  : g_offs;
    int* cur  = blockIdx.x ? g_curd  : g_curs;
    __shared__ int wsum[32];
    int t = threadIdx.x;         // 1024
    int lane = t & 31, wid = t >> 5;
    int4 a = ((const int4*)hist)[2*t];
    int4 b = ((const int4*)hist)[2*t+1];
    int l0=a.x, l1=l0+a.y, l2=l1+a.z, l3=l2+a.w;
    int l4=l3+b.x, l5=l4+b.y, l6=l5+b.z, l7=l6+b.w;
    int tot = l7;
    int pre = tot;
    #pragma unroll
    for (int o=1;o<32;o<<=1){ int v=__shfl_up_sync(0xffffffffu, pre, o); if (lane>=o) pre += v; }
    int wex = pre - tot;
    if (lane == 31) wsum[wid] = pre;
    __syncthreads();
    if (wid == 0){
        int v = wsum[lane];
        int p = v;
        #pragma unroll
        for (int o=1;o<32;o<<=1){ int u=__shfl_up_sync(0xffffffffu, p, o); if (lane>=o) p += u; }
        wsum[lane] = p - v;
    }
    __syncthreads();
    int base = wsum[wid] + wex;
    int4 o0 = make_int4(base,    base+l0, base+l1, base+l2);
    int4 o1 = make_int4(base+l3, base+l4, base+l5, base+l6);
    ((int4*)off)[2*t]   = o0;  ((int4*)off)[2*t+1] = o1;
    ((int4*)cur)[2*t]   = o0;  ((int4*)cur)[2*t+1] = o1;
    if (t == 1023) off[NN] = base + l7;
}

// ---------------- scatter halves ----------------------------------------------
__global__ void k_scat_s(const int* __restrict__ src, const int* __restrict__ dst){
    int e2 = blockIdx.x*blockDim.x + threadIdx.x;
    if (e2 >= EE/2) return;
    int2 s = ((const int2*)src)[e2];
    int2 d = ((const int2*)dst)[e2];
    uchar2 b = ((const uchar2*)g_bits)[e2];
    g_sent[atomicAdd(&g_curs[s.x], 1)] = d.x | (((int)b.x) << 14);
    g_sent[atomicAdd(&g_curs[s.y], 1)] = d.y | (((int)b.y) << 14);
}
__global__ void k_scat_d(const int* __restrict__ src, const int* __restrict__ dst){
    int e2 = blockIdx.x*blockDim.x + threadIdx.x;
    if (e2 >= EE/2) return;
    int2 s = ((const int2*)src)[e2];
    int2 d = ((const int2*)dst)[e2];
    uchar2 b = ((const uchar2*)g_bits)[e2];
    g_dent[atomicAdd(&g_curd[d.x], 1)] = s.x | (((int)b.x) << 14);
    g_dent[atomicAdd(&g_curd[d.y], 1)] = s.y | (((int)b.y) << 14);
}

// ---------------- k1: dedup weights + AH gather + Z + ft0 ---------------------
__global__ void k1(const float* __restrict__ h, const float* __restrict__ Ww,
                   const float* __restrict__ Wb, const float* __restrict__ fc0){
    __shared__ float sW[DD*DD];
    __shared__ float sF[DD*DD];
    __shared__ int   sd [8*512];
    __shared__ float srow[8][DD];
    int t = threadIdx.x;            // 256
    for (int x=t; x<DD*DD; x+=256){
        int k = x >> 6, j = x & 63;
        sW[x] = Ww[j*DD + k];
        sF[x] = fc0[x];
    }
    __syncthreads();
    int wl   = t >> 5;
    int lane = t & 31;
    int row  = blockIdx.x*8 + wl;
    int lo = g_offs[row], hi = g_offs[row+1];
    int L = hi - lo;
    float ax=0.f, ay=0.f;
    int*   my = sd + wl*512;
    if (L <= 512){
        for (int i=lane; i<L; i+=32) my[i] = g_sent[lo+i];
        __syncwarp();
        for (int i=lane; i<L; i+=32){
            int dv = my[i] & 0x3FFF; int c = 0;
            for (int j=0;j<L;j++) c += ((my[j]&0x3FFF)==dv);
            g_w0[lo+i] = 1.f/(float)c;
        }
        __syncwarp();
        #pragma unroll 4
        for (int i=0; i<L; i++){
            float w0 = g_w0[lo+i];
            float2 v = ((const float2*)(h + (size_t)(my[i] & 0x3FFF)*DD))[lane];
            ax += w0*v.x; ay += w0*v.y;
        }
    } else {
        for (int i=lane; i<L; i+=32){
            int dv = g_sent[lo+i] & 0x3FFF; int c = 0;
            for (int j=0;j<L;j++) c += ((g_sent[lo+j]&0x3FFF)==dv);
            g_w0[lo+i] = 1.f/(float)c;
        }
        __syncwarp();
        for (int i=lo; i<hi; i++){
            float w0 = g_w0[i];
            float2 v = ((const float2*)(h + (size_t)(g_sent[i] & 0x3FFF)*DD))[lane];
            ax += w0*v.x; ay += w0*v.y;
        }
    }
    srow[wl][2*lane] = ax; srow[wl][2*lane+1] = ay;
    __syncwarp();
    float2 z = ((const float2*)Wb)[lane];
    #pragma unroll 8
    for (int k=0;k<DD;k++){
        float a = srow[wl][k];
        float2 wv = ((const float2*)(sW + k*DD))[lane];
        z.x += a*wv.x; z.y += a*wv.y;
    }
    ((float2*)(g_Z + (size_t)row*DD))[lane] = z;
    __syncwarp();
    srow[wl][2*lane] = z.x; srow[wl][2*lane+1] = z.y;
    __syncwarp();
    float2 f = make_float2(0.f, 0.f);
    #pragma unroll 8
    for (int k=0;k<DD;k++){
        float a = srow[wl][k];
        float2 wv = ((const float2*)(sF + k*DD))[lane];
        f.x += a*wv.x; f.y += a*wv.y;
    }
    ((float2*)(g_ft0 + (size_t)row*DD))[lane] = f;
}

// ---------------- k2: AZ1/AZ2 gather + ft1/ft2 (16-lane groups) ---------------
__global__ void k2(const float* __restrict__ fc1, const float* __restrict__ fc2){
    __shared__ float sF1[DD*DD];
    __shared__ float sF2[DD*DD];
    __shared__ float srow[16][2*DD];
    int t = threadIdx.x;   // 256
    for (int x=t; x<DD*DD; x+=256){ sF1[x] = fc1[x]; sF2[x] = fc2[x]; }
    __syncthreads();
    int g  = t >> 4;
    int hl = t & 15;
    unsigned gmask = 0xFFFFu << (t & 16);
    int row = blockIdx.x*16 + g;
    int lo = g_offs[row], hi = g_offs[row+1];
    float4 acc1 = make_float4(0,0,0,0), acc2 = make_float4(0,0,0,0);
    #pragma unroll 4
    for (int i=lo; i<hi; i++){
        int w = g_sent[i];
        float w0 = g_w0[i];
        float w1 = (w & (1<<14)) ? w0 : 0.f;
        float w2 = (w & (1<<15)) ? w0 : 0.f;
        float4 v = ((const float4*)(g_Z + (size_t)(w & 0x3FFF)*DD))[hl];
        acc1.x += w1*v.x; acc1.y += w1*v.y; acc1.z += w1*v.z; acc1.w += w1*v.w;
        acc2.x += w2*v.x; acc2.y += w2*v.y; acc2.z += w2*v.z; acc2.w += w2*v.w;
    }
    ((float4*)&srow[g][0])[hl]  = acc1;
    ((float4*)&srow[g][DD])[hl] = acc2;
    __syncwarp(gmask);
    float4 f1 = make_float4(0,0,0,0), f2 = make_float4(0,0,0,0);
    #pragma unroll 8
    for (int k=0;k<DD;k++){
        float a1 = srow[g][k];
        float a2 = srow[g][DD+k];
        float4 w1 = ((const float4*)(sF1 + k*DD))[hl];
        float4 w2 = ((const float4*)(sF2 + k*DD))[hl];
        f1.x += a1*w1.x; f1.y += a1*w1.y; f1.z += a1*w1.z; f1.w += a1*w1.w;
        f2.x += a2*w2.x; f2.y += a2*w2.y; f2.z += a2*w2.z; f2.w += a2*w2.w;
    }
    ((float4*)(g_ft1 + (size_t)row*DD))[hl] = f1;
    ((float4*)(g_ft2 + (size_t)row*DD))[hl] = f2;
}

// ---------------- attention helpers ------------------------------------------
#define ONLINE_UPD4(m, den, acc, p, v) do {              \
    float _mn = fmaxf((m), (p));                         \
    float _sc = __expf((m) - _mn);                       \
    float _w  = __expf((p) - _mn);                       \
    (den) = (den)*_sc + _w;                              \
    (acc).x = (acc).x*_sc + _w*(v).x;                    \
    (acc).y = (acc).y*_sc + _w*(v).y;                    \
    (acc).z = (acc).z*_sc + _w*(v).z;                    \
    (acc).w = (acc).w*_sc + _w*(v).w;                    \
    (m) = _mn;                                           \
} while(0)

#define ONLINE_UPD4X2(m, den, acc, pa, va, pb, vb) do {  \
    float _mn = fmaxf((m), fmaxf((pa), (pb)));           \
    float _sc = __expf((m) - _mn);                       \
    float _wa = __expf((pa) - _mn);                      \
    float _wb = __expf((pb) - _mn);                      \
    (den) = (den)*_sc + _wa + _wb;                       \
    (acc).x = (acc).x*_sc + _wa*(va).x + _wb*(vb).x;     \
    (acc).y = (acc).y*_sc + _wa*(va).y + _wb*(vb).y;     \
    (acc).z = (acc).z*_sc + _wa*(va).z + _wb*(vb).z;     \
    (acc).w = (acc).w*_sc + _wa*(va).w + _wb*(vb).w;     \
    (m) = _mn;                                           \
} while(0)

__device__ __forceinline__ float red16(float p, unsigned gmask){
    #pragma unroll
    for (int o=8;o;o>>=1) p += __shfl_xor_sync(gmask, p, o);
    return p;
}
__device__ __forceinline__ float dot4(float4 a, float4 b){
    return a.x*b.x + a.y*b.y + a.z*b.z + a.w*b.w;
}

// ---------------- attn0: motif 0 (runs ∥ with k2) -----------------------------
__global__ void k_attn0(){
    __shared__ float sacc[DD];
    int t = threadIdx.x;
    if (t < DD) sacc[t] = 0.f;
    __syncthreads();
    int hl = t & 15;
    unsigned gmask = 0xFFFFu << (t & 16);
    int d  = (blockIdx.x*256 + t) >> 4;
    if (d < NN){
        int lo = g_offd[d], hi = g_offd[d+1];
        if (lo < hi){
            float4 f0 = ((const float4*)(g_ft0 + (size_t)d*DD))[hl];
            float m0=-FLT_MAX, den0=0.f; float4 a0 = make_float4(0,0,0,0);
            int i = lo;
            for (; i+1 < hi; i += 2){
                int sa = g_dent[i]   & 0x3FFF;
                int sb = g_dent[i+1] & 0x3FFF;
                float4 va = ((const float4*)(g_ft0 + (size_t)sa*DD))[hl];
                float4 vb = ((const float4*)(g_ft0 + (size_t)sb*DD))[hl];
                float pa = red16(dot4(va, f0), gmask) * 0.125f;
                float pb = red16(dot4(vb, f0), gmask) * 0.125f;
                ONLINE_UPD4X2(m0, den0, a0, pa, va, pb, vb);
            }
            if (i < hi){
                int s = g_dent[i] & 0x3FFF;
                float4 v0 = ((const float4*)(g_ft0 + (size_t)s*DD))[hl];
                float p0 = red16(dot4(v0, f0), gmask) * 0.125f;
                ONLINE_UPD4(m0, den0, a0, p0, v0);
            }
            float r0 = 1.f/fmaxf(den0, 1e-9f);
            atomicAdd(&sacc[4*hl+0], a0.x*r0); atomicAdd(&sacc[4*hl+1], a0.y*r0);
            atomicAdd(&sacc[4*hl+2], a0.z*r0); atomicAdd(&sacc[4*hl+3], a0.w*r0);
        }
    }
    __syncthreads();
    if (t < DD) atomicAdd(&g_pool[t], sacc[t]);
}

// ---------------- attn12: motifs 1 & 2 ----------------------------------------
__global__ void k_attn12(){
    __shared__ float sacc[2*DD];
    int t = threadIdx.x;
    for (int j=t; j<2*DD; j+=256) sacc[j] = 0.f;
    __syncthreads();
    int hl = t & 15;
    unsigned gmask = 0xFFFFu << (t & 16);
    int d  = (blockIdx.x*256 + t) >> 4;
    if (d < NN){
        int lo = g_offd[d], hi = g_offd[d+1];
        if (lo < hi){
            float4 f1 = ((const float4*)(g_ft1 + (size_t)d*DD))[hl];
            float4 f2 = ((const float4*)(g_ft2 + (size_t)d*DD))[hl];
            float m1=-FLT_MAX, den1=0.f; float4 a1 = make_float4(0,0,0,0);
            float m2=-FLT_MAX, den2=0.f; float4 a2 = make_float4(0,0,0,0);
            for (int i=lo; i<hi; i++){
                int w = g_dent[i];
                int s = w & 0x3FFF;
                if (w & (1<<14)){
                    float4 v1 = ((const float4*)(g_ft1 + (size_t)s*DD))[hl];
                    float p1 = red16(dot4(v1, f1), gmask) * 0.125f;
                    ONLINE_UPD4(m1, den1, a1, p1, v1);
                    if (hl == 0){ g_nm1[s] = 1; g_nm1[d] = 1; }
                }
                if (w & (1<<15)){
                    float4 v2 = ((const float4*)(g_ft2 + (size_t)s*DD))[hl];
                    float p2 = red16(dot4(v2, f2), gmask) * 0.125f;
                    ONLINE_UPD4(m2, den2, a2, p2, v2);
                    if (hl == 0){ g_nm2[s] = 1; g_nm2[d] = 1; }
                }
            }
            if (den1 > 0.f){
                float r1 = 1.f/den1;
                atomicAdd(&sacc[4*hl+0], a1.x*r1); atomicAdd(&sacc[4*hl+1], a1.y*r1);
                atomicAdd(&sacc[4*hl+2], a1.z*r1); atomicAdd(&sacc[4*hl+3], a1.w*r1);
            }
            if (den2 > 0.f){
                float r2 = 1.f/den2;
                atomicAdd(&sacc[DD+4*hl+0], a2.x*r2); atomicAdd(&sacc[DD+4*hl+1], a2.y*r2);
                atomicAdd(&sacc[DD+4*hl+2], a2.z*r2); atomicAdd(&sacc[DD+4*hl+3], a2.w*r2);
            }
        }
    }
    __syncthreads();
    for (int j=t; j<2*DD; j+=256) atomicAdd(&g_pool[DD+j], sacc[j]);
}

// ---------------- node counts + final linear ----------------------------------
__global__ void k_nfinal(const float* __restrict__ lw, const float* __restrict__ lb,
                         float* __restrict__ out){
    __shared__ int sc1, sc2;
    __shared__ float s0[3*DD], s1[3*DD];
    int t = threadIdx.x;   // 256
    if (t == 0){ sc1 = 0; sc2 = 0; }
    __syncthreads();
    int c1 = 0, c2 = 0;
    for (int i=t; i<NN; i+=256){ c1 += g_nm1[i]; c2 += g_nm2[i]; }
    #pragma unroll
    for (int o=16;o;o>>=1){
        c1 += __shfl_xor_sync(0xffffffffu, c1, o);
        c2 += __shfl_xor_sync(0xffffffffu, c2, o);
    }
    if ((t & 31) == 0){ atomicAdd(&sc1, c1); atomicAdd(&sc2, c2); }
    __syncthreads();
    if (t < 3*DD){
        int k = t >> 6;
        float cnt = (k==0) ? (float)NN : fmaxf((float)(k==1 ? sc1 : sc2), 1.f);
        float p = g_pool[t] / cnt;
        s0[t] = p * lw[t*2 + 0];
        s1[t] = p * lw[t*2 + 1];
    }
    __syncthreads();
    if (t == 0){
        float a = 0.f, b = 0.f;
        for (int i=0;i<3*DD;i++){ a += s0[i]; b += s1[i]; }
        out[0] = a + lb[0];
        out[1] = b + lb[1];
    }
}

// ---------------- host launcher -----------------------------------------------
// ALL work on created non-blocking streams; the legacy stream (capture origin)
// only forks/joins. Legacy-stream launches would serialize the whole graph via
// implicit sync — that's why R8/R9 overlap was a no-op.
static cudaStream_t get_stream(int i){
    static cudaStream_t s[2] = {nullptr, nullptr};
    if (!s[i]) cudaStreamCreateWithFlags(&s[i], cudaStreamNonBlocking);
    return s[i];
}
static cudaEvent_t get_ev(int i){
    static cudaEvent_t e[8] = {};
    if (!e[i]) cudaEventCreateWithFlags(&e[i], cudaEventDisableTiming);
    return e[i];
}

extern "C" void kernel_launch(void* const* d_in, const int* in_sizes, int n_in,
                              void* d_out, int out_size){
    const float* h    = (const float*)d_in[0];
    const float* A1   = (const float*)d_in[2];
    const float* A2   = (const float*)d_in[3];
    const float* Ww   = (const float*)d_in[4];
    const float* Wb   = (const float*)d_in[5];
    const float* fc0  = (const float*)d_in[6];
    const float* fc1  = (const float*)d_in[7];
    const float* fc2  = (const float*)d_in[8];
    const float* linw = (const float*)d_in[9];
    const float* linb = (const float*)d_in[10];
    const int*   src  = (const int*)d_in[11];
    const int*   dst  = (const int*)d_in[12];
    float* out = (float*)d_out;

    cudaStream_t s1 = get_stream(0);
    cudaStream_t s2 = get_stream(1);
    cudaEvent_t evFork = get_ev(0);
    cudaEvent_t evBits = get_ev(1);
    cudaEvent_t evScan = get_ev(2);
    cudaEvent_t evDent = get_ev(3);
    cudaEvent_t evFt0  = get_ev(4);
    cudaEvent_t evA0   = get_ev(5);
    cudaEvent_t evDone = get_ev(6);

    // fork from capture-origin (legacy) stream
    cudaEventRecord(evFork, 0);
    cudaStreamWaitEvent(s1, evFork, 0);
    cudaStreamWaitEvent(s2, evFork, 0);

    // s1: bits probe -> dent scatter -> attn0
    k_bits   <<<512,  256, 0, s1>>>(src, dst, A1, A2);
    cudaEventRecord(evBits, s1);

    // s2: init -> hist -> scan -> sent scatter -> k1 -> k2 -> attn12 -> nfinal
    k_init   <<<64,   256, 0, s2>>>();
    k_hist   <<<512,  256, 0, s2>>>(src, dst);
    k_scan   <<<2,   1024, 0, s2>>>();
    cudaEventRecord(evScan, s2);

    cudaStreamWaitEvent(s1, evScan, 0);
    k_scat_d <<<1024, 256, 0, s1>>>(src, dst);
    cudaEventRecord(evDent, s1);

    cudaStreamWaitEvent(s2, evBits, 0);
    k_scat_s <<<1024, 256, 0, s2>>>(src, dst);
    k1       <<<1024, 256, 0, s2>>>(h, Ww, Wb, fc0);
    cudaEventRecord(evFt0, s2);

    // s1: attn0 needs ft0 (evFt0) + dent (s1 order) + init (implied by evFt0)
    cudaStreamWaitEvent(s1, evFt0, 0);
    k_attn0  <<<512,  256, 0, s1>>>();
    cudaEventRecord(evA0, s1);

    // s2: k2 ∥ attn0, then attn12 (needs dent), then final
    k2       <<<512,  256, 0, s2>>>(fc1, fc2);
    cudaStreamWaitEvent(s2, evDent, 0);
    k_attn12 <<<512,  256, 0, s2>>>();
    cudaStreamWaitEvent(s2, evA0, 0);
    k_nfinal <<<1,    256, 0, s2>>>(linw, linb, out);
    cudaEventRecord(evDone, s2);

    // join back to origin stream
    cudaStreamWaitEvent(0, evDone, 0);
    (void)in_sizes; (void)n_in; (void)out_size;
}

// round 11
// speedup vs baseline: 2.4074x; 1.0365x over previous
#include <cuda_runtime.h>
#include <math.h>
#include <float.h>

#define NN 8192
#define DD 64
#define EE 524288

// ---------------- static device scratch -------------------------------------
// Zero-initialized at module load. Every kernel that consumes transient state
// re-zeroes it after reading, so each graph replay starts clean.
__device__ __align__(16) float g_Z  [NN*DD];
__device__ __align__(16) float g_ft0[NN*DD];
__device__ __align__(16) float g_ft1[NN*DD];
__device__ __align__(16) float g_ft2[NN*DD];
__device__ __align__(16) float g_w0 [EE];
__device__ __align__(16) int   g_sent[EE];     // dst | m1<<14 | m2<<15 (src-CSR)
__device__ __align__(16) int   g_dent[EE];     // src | m1<<14 | m2<<15 (dst-CSR)
__device__ __align__(16) unsigned char g_bits[EE];
__device__ __align__(16) int   g_hists[NN];
__device__ __align__(16) int   g_histd[NN];
__device__ __align__(16) int   g_offs[NN+8];
__device__ __align__(16) int   g_offd[NN+8];
__device__ __align__(16) int   g_curs[NN];
__device__ __align__(16) int   g_curd[NN];
__device__ int   g_nm1[NN], g_nm2[NN];
__device__ float g_pool[3*DD];

// ---------------- hist + A1/A2 mask probes (fused; 4 edges/thread) -----------
__global__ void k_histbits(const int* __restrict__ src, const int* __restrict__ dst,
                           const float* __restrict__ A1, const float* __restrict__ A2){
    int e4 = blockIdx.x*blockDim.x + threadIdx.x;
    if (e4 >= EE/4) return;
    int4 s = ((const int4*)src)[e4];
    int4 d = ((const int4*)dst)[e4];
    float a1x = __ldcs(&A1[(size_t)s.x*NN + d.x]);
    float a1y = __ldcs(&A1[(size_t)s.y*NN + d.y]);
    float a1z = __ldcs(&A1[(size_t)s.z*NN + d.z]);
    float a1w = __ldcs(&A1[(size_t)s.w*NN + d.w]);
    float a2x = __ldcs(&A2[(size_t)s.x*NN + d.x]);
    float a2y = __ldcs(&A2[(size_t)s.y*NN + d.y]);
    float a2z = __ldcs(&A2[(size_t)s.z*NN + d.z]);
    float a2w = __ldcs(&A2[(size_t)s.w*NN + d.w]);
    atomicAdd(&g_hists[s.x], 1); atomicAdd(&g_hists[s.y], 1);
    atomicAdd(&g_hists[s.z], 1); atomicAdd(&g_hists[s.w], 1);
    atomicAdd(&g_histd[d.x], 1); atomicAdd(&g_histd[d.y], 1);
    atomicAdd(&g_histd[d.z], 1); atomicAdd(&g_histd[d.w], 1);
    uchar4 b;
    b.x = (unsigned char)(((a1x > 0.f) ? 1 : 0) | ((a2x > 0.f) ? 2 : 0));
    b.y = (unsigned char)(((a1y > 0.f) ? 1 : 0) | ((a2y > 0.f) ? 2 : 0));
    b.z = (unsigned char)(((a1z > 0.f) ? 1 : 0) | ((a2z > 0.f) ? 2 : 0));
    b.w = (unsigned char)(((a1w > 0.f) ? 1 : 0) | ((a2w > 0.f) ? 2 : 0));
    ((uchar4*)g_bits)[e4] = b;
}

// ---------------- fast scan (2 barriers) + self-clean hist --------------------
__global__ void k_scan(){
    int* hist = blockIdx.x ? g_histd : g_hists;
    int* off  = blockIdx.x ? g_offd  : g_offs;
    int* cur  = blockIdx.x ? g_curd  : g_curs;
    __shared__ int wsum[32];
    int t = threadIdx.x;         // 1024
    int lane = t & 31, wid = t >> 5;
    int4 a = ((const int4*)hist)[2*t];
    int4 b = ((const int4*)hist)[2*t+1];
    int l0=a.x, l1=l0+a.y, l2=l1+a.z, l3=l2+a.w;
    int l4=l3+b.x, l5=l4+b.y, l6=l5+b.z, l7=l6+b.w;
    // zero hist for the next replay (each entry read only by this thread)
    int4 z4 = make_int4(0,0,0,0);
    ((int4*)hist)[2*t]   = z4;
    ((int4*)hist)[2*t+1] = z4;
    int tot = l7;
    int pre = tot;
    #pragma unroll
    for (int o=1;o<32;o<<=1){ int v=__shfl_up_sync(0xffffffffu, pre, o); if (lane>=o) pre += v; }
    int wex = pre - tot;
    if (lane == 31) wsum[wid] = pre;
    __syncthreads();
    if (wid == 0){
        int v = wsum[lane];
        int p = v;
        #pragma unroll
        for (int o=1;o<32;o<<=1){ int u=__shfl_up_sync(0xffffffffu, p, o); if (lane>=o) p += u; }
        wsum[lane] = p - v;
    }
    __syncthreads();
    int base = wsum[wid] + wex;
    int4 o0 = make_int4(base,    base+l0, base+l1, base+l2);
    int4 o1 = make_int4(base+l3, base+l4, base+l5, base+l6);
    ((int4*)off)[2*t]   = o0;  ((int4*)off)[2*t+1] = o1;
    ((int4*)cur)[2*t]   = o0;  ((int4*)cur)[2*t+1] = o1;
    if (t == 1023) off[NN] = base + l7;
}

// ---------------- scatter (both CSRs, one edge pass) ---------------------------
__global__ void k_scatter(const int* __restrict__ src, const int* __restrict__ dst){
    int e2 = blockIdx.x*blockDim.x + threadIdx.x;
    if (e2 >= EE/2) return;
    int2 s = ((const int2*)src)[e2];
    int2 d = ((const int2*)dst)[e2];
    uchar2 b = ((const uchar2*)g_bits)[e2];
    int bx = ((int)b.x) << 14;
    int by = ((int)b.y) << 14;
    g_sent[atomicAdd(&g_curs[s.x], 1)] = d.x | bx;
    g_dent[atomicAdd(&g_curd[d.x], 1)] = s.x | bx;
    g_sent[atomicAdd(&g_curs[s.y], 1)] = d.y | by;
    g_dent[atomicAdd(&g_curd[d.y], 1)] = s.y | by;
}

// ---------------- k1: dedup weights + AH gather + Z + ft0 ---------------------
__global__ void k1(const float* __restrict__ h, const float* __restrict__ Ww,
                   const float* __restrict__ Wb, const float* __restrict__ fc0){
    __shared__ float sW[DD*DD];
    __shared__ float sF[DD*DD];
    __shared__ int   sd [8*512];
    __shared__ float srow[8][DD];
    int t = threadIdx.x;            // 256
    for (int x=t; x<DD*DD; x+=256){
        int k = x >> 6, j = x & 63;
        sW[x] = Ww[j*DD + k];
        sF[x] = fc0[x];
    }
    __syncthreads();
    int wl   = t >> 5;
    int lane = t & 31;
    int row  = blockIdx.x*8 + wl;
    int lo = g_offs[row], hi = g_offs[row+1];
    int L = hi - lo;
    float ax=0.f, ay=0.f;
    int*   my = sd + wl*512;
    if (L <= 512){
        for (int i=lane; i<L; i+=32) my[i] = g_sent[lo+i];
        __syncwarp();
        for (int i=lane; i<L; i+=32){
            int dv = my[i] & 0x3FFF; int c = 0;
            for (int j=0;j<L;j++) c += ((my[j]&0x3FFF)==dv);
            g_w0[lo+i] = 1.f/(float)c;
        }
        __syncwarp();
        #pragma unroll 4
        for (int i=0; i<L; i++){
            float w0 = g_w0[lo+i];
            float2 v = ((const float2*)(h + (size_t)(my[i] & 0x3FFF)*DD))[lane];
            ax += w0*v.x; ay += w0*v.y;
        }
    } else {
        for (int i=lane; i<L; i+=32){
            int dv = g_sent[lo+i] & 0x3FFF; int c = 0;
            for (int j=0;j<L;j++) c += ((g_sent[lo+j]&0x3FFF)==dv);
            g_w0[lo+i] = 1.f/(float)c;
        }
        __syncwarp();
        for (int i=lo; i<hi; i++){
            float w0 = g_w0[i];
            float2 v = ((const float2*)(h + (size_t)(g_sent[i] & 0x3FFF)*DD))[lane];
            ax += w0*v.x; ay += w0*v.y;
        }
    }
    srow[wl][2*lane] = ax; srow[wl][2*lane+1] = ay;
    __syncwarp();
    float2 z = ((const float2*)Wb)[lane];
    #pragma unroll 8
    for (int k=0;k<DD;k++){
        float a = srow[wl][k];
        float2 wv = ((const float2*)(sW + k*DD))[lane];
        z.x += a*wv.x; z.y += a*wv.y;
    }
    ((float2*)(g_Z + (size_t)row*DD))[lane] = z;
    __syncwarp();
    srow[wl][2*lane] = z.x; srow[wl][2*lane+1] = z.y;
    __syncwarp();
    float2 f = make_float2(0.f, 0.f);
    #pragma unroll 8
    for (int k=0;k<DD;k++){
        float a = srow[wl][k];
        float2 wv = ((const float2*)(sF + k*DD))[lane];
        f.x += a*wv.x; f.y += a*wv.y;
    }
    ((float2*)(g_ft0 + (size_t)row*DD))[lane] = f;
}

// ---------------- k2: AZ1/AZ2 gather + ft1/ft2 (16-lane groups) ---------------
__global__ void k2(const float* __restrict__ fc1, const float* __restrict__ fc2){
    __shared__ float sF1[DD*DD];
    __shared__ float sF2[DD*DD];
    __shared__ float srow[16][2*DD];
    int t = threadIdx.x;   // 256
    for (int x=t; x<DD*DD; x+=256){ sF1[x] = fc1[x]; sF2[x] = fc2[x]; }
    __syncthreads();
    int g  = t >> 4;
    int hl = t & 15;
    unsigned gmask = 0xFFFFu << (t & 16);
    int row = blockIdx.x*16 + g;
    int lo = g_offs[row], hi = g_offs[row+1];
    float4 acc1 = make_float4(0,0,0,0), acc2 = make_float4(0,0,0,0);
    #pragma unroll 4
    for (int i=lo; i<hi; i++){
        int w = g_sent[i];
        float w0 = g_w0[i];
        float w1 = (w & (1<<14)) ? w0 : 0.f;
        float w2 = (w & (1<<15)) ? w0 : 0.f;
        float4 v = ((const float4*)(g_Z + (size_t)(w & 0x3FFF)*DD))[hl];
        acc1.x += w1*v.x; acc1.y += w1*v.y; acc1.z += w1*v.z; acc1.w += w1*v.w;
        acc2.x += w2*v.x; acc2.y += w2*v.y; acc2.z += w2*v.z; acc2.w += w2*v.w;
    }
    ((float4*)&srow[g][0])[hl]  = acc1;
    ((float4*)&srow[g][DD])[hl] = acc2;
    __syncwarp(gmask);
    float4 f1 = make_float4(0,0,0,0), f2 = make_float4(0,0,0,0);
    #pragma unroll 8
    for (int k=0;k<DD;k++){
        float a1 = srow[g][k];
        float a2 = srow[g][DD+k];
        float4 w1 = ((const float4*)(sF1 + k*DD))[hl];
        float4 w2 = ((const float4*)(sF2 + k*DD))[hl];
        f1.x += a1*w1.x; f1.y += a1*w1.y; f1.z += a1*w1.z; f1.w += a1*w1.w;
        f2.x += a2*w2.x; f2.y += a2*w2.y; f2.z += a2*w2.z; f2.w += a2*w2.w;
    }
    ((float4*)(g_ft1 + (size_t)row*DD))[hl] = f1;
    ((float4*)(g_ft2 + (size_t)row*DD))[hl] = f2;
}

// ---------------- fused attention (all 3 motifs, 16-lane groups) --------------
#define ONLINE_UPD4(m, den, acc, p, v) do {              \
    float _mn = fmaxf((m), (p));                         \
    float _sc = __expf((m) - _mn);                       \
    float _w  = __expf((p) - _mn);                       \
    (den) = (den)*_sc + _w;                              \
    (acc).x = (acc).x*_sc + _w*(v).x;                    \
    (acc).y = (acc).y*_sc + _w*(v).y;                    \
    (acc).z = (acc).z*_sc + _w*(v).z;                    \
    (acc).w = (acc).w*_sc + _w*(v).w;                    \
    (m) = _mn;                                           \
} while(0)

#define ONLINE_UPD4X2(m, den, acc, pa, va, pb, vb) do {  \
    float _mn = fmaxf((m), fmaxf((pa), (pb)));           \
    float _sc = __expf((m) - _mn);                       \
    float _wa = __expf((pa) - _mn);                      \
    float _wb = __expf((pb) - _mn);                      \
    (den) = (den)*_sc + _wa + _wb;                       \
    (acc).x = (acc).x*_sc + _wa*(va).x + _wb*(vb).x;     \
    (acc).y = (acc).y*_sc + _wa*(va).y + _wb*(vb).y;     \
    (acc).z = (acc).z*_sc + _wa*(va).z + _wb*(vb).z;     \
    (acc).w = (acc).w*_sc + _wa*(va).w + _wb*(vb).w;     \
    (m) = _mn;                                           \
} while(0)

__device__ __forceinline__ float red16(float p, unsigned gmask){
    #pragma unroll
    for (int o=8;o;o>>=1) p += __shfl_xor_sync(gmask, p, o);
    return p;
}
__device__ __forceinline__ float dot4(float4 a, float4 b){
    return a.x*b.x + a.y*b.y + a.z*b.z + a.w*b.w;
}

__global__ void k_attn(){
    __shared__ float sacc[3*DD];
    int t = threadIdx.x;
    for (int j=t; j<3*DD; j+=256) sacc[j] = 0.f;
    __syncthreads();
    int hl = t & 15;
    unsigned gmask = 0xFFFFu << (t & 16);
    int d  = (blockIdx.x*256 + t) >> 4;       // one dst row per 16-group
    if (d < NN){
        int lo = g_offd[d], hi = g_offd[d+1];
        if (lo < hi){
            float4 f0 = ((const float4*)(g_ft0 + (size_t)d*DD))[hl];
            float4 f1 = ((const float4*)(g_ft1 + (size_t)d*DD))[hl];
            float4 f2 = ((const float4*)(g_ft2 + (size_t)d*DD))[hl];
            float m0=-FLT_MAX, den0=0.f; float4 a0 = make_float4(0,0,0,0);
            float m1=-FLT_MAX, den1=0.f; float4 a1 = make_float4(0,0,0,0);
            float m2=-FLT_MAX, den2=0.f; float4 a2 = make_float4(0,0,0,0);
            int i = lo;
            for (; i+1 < hi; i += 2){
                int wa = g_dent[i];
                int wb = g_dent[i+1];
                int sa = wa & 0x3FFF, sb = wb & 0x3FFF;
                float4 va = ((const float4*)(g_ft0 + (size_t)sa*DD))[hl];
                float4 vb = ((const float4*)(g_ft0 + (size_t)sb*DD))[hl];
                float pa = red16(dot4(va, f0), gmask) * 0.125f;
                float pb = red16(dot4(vb, f0), gmask) * 0.125f;
                ONLINE_UPD4X2(m0, den0, a0, pa, va, pb, vb);
                if (wa & (1<<14)){
                    float4 v1 = ((const float4*)(g_ft1 + (size_t)sa*DD))[hl];
                    float p1 = red16(dot4(v1, f1), gmask) * 0.125f;
                    ONLINE_UPD4(m1, den1, a1, p1, v1);
                    if (hl == 0){ g_nm1[sa] = 1; g_nm1[d] = 1; }
                }
                if (wb & (1<<14)){
                    float4 v1 = ((const float4*)(g_ft1 + (size_t)sb*DD))[hl];
                    float p1 = red16(dot4(v1, f1), gmask) * 0.125f;
                    ONLINE_UPD4(m1, den1, a1, p1, v1);
                    if (hl == 0){ g_nm1[sb] = 1; g_nm1[d] = 1; }
                }
                if (wa & (1<<15)){
                    float4 v2 = ((const float4*)(g_ft2 + (size_t)sa*DD))[hl];
                    float p2 = red16(dot4(v2, f2), gmask) * 0.125f;
                    ONLINE_UPD4(m2, den2, a2, p2, v2);
                    if (hl == 0){ g_nm2[sa] = 1; g_nm2[d] = 1; }
                }
                if (wb & (1<<15)){
                    float4 v2 = ((const float4*)(g_ft2 + (size_t)sb*DD))[hl];
                    float p2 = red16(dot4(v2, f2), gmask) * 0.125f;
                    ONLINE_UPD4(m2, den2, a2, p2, v2);
                    if (hl == 0){ g_nm2[sb] = 1; g_nm2[d] = 1; }
                }
            }
            if (i < hi){
                int w = g_dent[i];
                int s = w & 0x3FFF;
                float4 v0 = ((const float4*)(g_ft0 + (size_t)s*DD))[hl];
                float p0 = red16(dot4(v0, f0), gmask) * 0.125f;
                ONLINE_UPD4(m0, den0, a0, p0, v0);
                if (w & (1<<14)){
                    float4 v1 = ((const float4*)(g_ft1 + (size_t)s*DD))[hl];
                    float p1 = red16(dot4(v1, f1), gmask) * 0.125f;
                    ONLINE_UPD4(m1, den1, a1, p1, v1);
                    if (hl == 0){ g_nm1[s] = 1; g_nm1[d] = 1; }
                }
                if (w & (1<<15)){
                    float4 v2 = ((const float4*)(g_ft2 + (size_t)s*DD))[hl];
                    float p2 = red16(dot4(v2, f2), gmask) * 0.125f;
                    ONLINE_UPD4(m2, den2, a2, p2, v2);
                    if (hl == 0){ g_nm2[s] = 1; g_nm2[d] = 1; }
                }
            }
            float r0 = 1.f/fmaxf(den0, 1e-9f);
            atomicAdd(&sacc[4*hl+0], a0.x*r0); atomicAdd(&sacc[4*hl+1], a0.y*r0);
            atomicAdd(&sacc[4*hl+2], a0.z*r0); atomicAdd(&sacc[4*hl+3], a0.w*r0);
            if (den1 > 0.f){
                float r1 = 1.f/den1;
                atomicAdd(&sacc[DD+4*hl+0], a1.x*r1); atomicAdd(&sacc[DD+4*hl+1], a1.y*r1);
                atomicAdd(&sacc[DD+4*hl+2], a1.z*r1); atomicAdd(&sacc[DD+4*hl+3], a1.w*r1);
            }
            if (den2 > 0.f){
                float r2 = 1.f/den2;
                atomicAdd(&sacc[2*DD+4*hl+0], a2.x*r2); atomicAdd(&sacc[2*DD+4*hl+1], a2.y*r2);
                atomicAdd(&sacc[2*DD+4*hl+2], a2.z*r2); atomicAdd(&sacc[2*DD+4*hl+3], a2.w*r2);
            }
        }
    }
    __syncthreads();
    for (int j=t; j<3*DD; j+=256) atomicAdd(&g_pool[j], sacc[j]);
}

// ---------------- counts + final linear + self-clean ---------------------------
__global__ void k_nfinal(const float* __restrict__ lw, const float* __restrict__ lb,
                         float* __restrict__ out){
    __shared__ int sc1, sc2;
    __shared__ float s0[3*DD], s1[3*DD];
    int t = threadIdx.x;   // 256
    if (t == 0){ sc1 = 0; sc2 = 0; }
    __syncthreads();
    int c1 = 0, c2 = 0;
    for (int i=t; i<NN; i+=256){
        c1 += g_nm1[i];  g_nm1[i] = 0;      // read + clean for next replay
        c2 += g_nm2[i];  g_nm2[i] = 0;
    }
    #pragma unroll
    for (int o=16;o;o>>=1){
        c1 += __shfl_xor_sync(0xffffffffu, c1, o);
        c2 += __shfl_xor_sync(0xffffffffu, c2, o);
    }
    if ((t & 31) == 0){ atomicAdd(&sc1, c1); atomicAdd(&sc2, c2); }
    __syncthreads();
    if (t < 3*DD){
        int k = t >> 6;
        float cnt = (k==0) ? (float)NN : fmaxf((float)(k==1 ? sc1 : sc2), 1.f);
        float p = g_pool[t] / cnt;
        g_pool[t] = 0.f;                     // clean for next replay
        s0[t] = p * lw[t*2 + 0];
        s1[t] = p * lw[t*2 + 1];
    }
    __syncthreads();
    if (t == 0){
        float a = 0.f, b = 0.f;
        for (int i=0;i<3*DD;i++){ a += s0[i]; b += s1[i]; }
        out[0] = a + lb[0];
        out[1] = b + lb[1];
    }
}

// ---------------- host launcher -----------------------------------------------
extern "C" void kernel_launch(void* const* d_in, const int* in_sizes, int n_in,
                              void* d_out, int out_size){
    const float* h    = (const float*)d_in[0];
    const float* A1   = (const float*)d_in[2];
    const float* A2   = (const float*)d_in[3];
    const float* Ww   = (const float*)d_in[4];
    const float* Wb   = (const float*)d_in[5];
    const float* fc0  = (const float*)d_in[6];
    const float* fc1  = (const float*)d_in[7];
    const float* fc2  = (const float*)d_in[8];
    const float* linw = (const float*)d_in[9];
    const float* linb = (const float*)d_in[10];
    const int*   src  = (const int*)d_in[11];
    const int*   dst  = (const int*)d_in[12];
    float* out = (float*)d_out;

    k_histbits<<<512,  256>>>(src, dst, A1, A2);
    k_scan    <<<2,   1024>>>();
    k_scatter <<<1024, 256>>>(src, dst);
    k1        <<<1024, 256>>>(h, Ww, Wb, fc0);
    k2        <<<512,  256>>>(fc1, fc2);
    k_attn    <<<512,  256>>>();
    k_nfinal  <<<1,    256>>>(linw, linb, out);
    (void)in_sizes; (void)n_in; (void)out_size;
}

// round 12
// speedup vs baseline: 2.5581x; 1.0626x over previous
#include <cuda_runtime.h>
#include <math.h>
#include <float.h>

#define NN 8192
#define DD 64
#define EE 524288

// ---------------- static device scratch -------------------------------------
// Zero-initialized at module load; every consumer kernel re-zeroes what it
// consumed, so each graph replay starts clean.
__device__ __align__(16) float g_Z  [NN*DD];
__device__ __align__(16) float g_ft0[NN*DD];
__device__ __align__(16) float g_ft1[NN*DD];
__device__ __align__(16) float g_ft2[NN*DD];
__device__ __align__(16) float g_w0 [EE];
__device__ __align__(16) int   g_sent[EE];     // dst | m1<<14 | m2<<15 (src-CSR)
__device__ __align__(16) int   g_dent[EE];     // src | m1<<14 | m2<<15 (dst-CSR)
__device__ __align__(16) unsigned char g_bits[EE];
__device__ __align__(16) unsigned g_mult[1<<24];  // 64MB: 4 byte-counters/int, key=(s<<13)|d
__device__ __align__(16) int   g_hists[NN];
__device__ __align__(16) int   g_histd[NN];
__device__ __align__(16) int   g_offs[NN+8];
__device__ __align__(16) int   g_offd[NN+8];
__device__ __align__(16) int   g_curs[NN];
__device__ __align__(16) int   g_curd[NN];
__device__ int   g_nm1[NN], g_nm2[NN];          // rewritten fully every run
__device__ float g_pool[3*DD];

// ---------------- hist + A1/A2 probes + multiplicity count (fused) -----------
__global__ void k_histbits(const int* __restrict__ src, const int* __restrict__ dst,
                           const float* __restrict__ A1, const float* __restrict__ A2){
    int e4 = blockIdx.x*blockDim.x + threadIdx.x;
    if (e4 >= EE/4) return;
    int4 s = ((const int4*)src)[e4];
    int4 d = ((const int4*)dst)[e4];
    float a1x = __ldcs(&A1[(size_t)s.x*NN + d.x]);
    float a1y = __ldcs(&A1[(size_t)s.y*NN + d.y]);
    float a1z = __ldcs(&A1[(size_t)s.z*NN + d.z]);
    float a1w = __ldcs(&A1[(size_t)s.w*NN + d.w]);
    float a2x = __ldcs(&A2[(size_t)s.x*NN + d.x]);
    float a2y = __ldcs(&A2[(size_t)s.y*NN + d.y]);
    float a2z = __ldcs(&A2[(size_t)s.z*NN + d.z]);
    float a2w = __ldcs(&A2[(size_t)s.w*NN + d.w]);
    int kx = (s.x<<13)|d.x, ky = (s.y<<13)|d.y, kz = (s.z<<13)|d.z, kw = (s.w<<13)|d.w;
    atomicAdd(&g_mult[kx>>2], 1u<<((kx&3)*8));
    atomicAdd(&g_mult[ky>>2], 1u<<((ky&3)*8));
    atomicAdd(&g_mult[kz>>2], 1u<<((kz&3)*8));
    atomicAdd(&g_mult[kw>>2], 1u<<((kw&3)*8));
    atomicAdd(&g_hists[s.x], 1); atomicAdd(&g_hists[s.y], 1);
    atomicAdd(&g_hists[s.z], 1); atomicAdd(&g_hists[s.w], 1);
    atomicAdd(&g_histd[d.x], 1); atomicAdd(&g_histd[d.y], 1);
    atomicAdd(&g_histd[d.z], 1); atomicAdd(&g_histd[d.w], 1);
    uchar4 b;
    b.x = (unsigned char)(((a1x > 0.f) ? 1 : 0) | ((a2x > 0.f) ? 2 : 0));
    b.y = (unsigned char)(((a1y > 0.f) ? 1 : 0) | ((a2y > 0.f) ? 2 : 0));
    b.z = (unsigned char)(((a1z > 0.f) ? 1 : 0) | ((a2z > 0.f) ? 2 : 0));
    b.w = (unsigned char)(((a1w > 0.f) ? 1 : 0) | ((a2w > 0.f) ? 2 : 0));
    ((uchar4*)g_bits)[e4] = b;
}

// ---------------- fast scan (2 barriers) + self-clean hist --------------------
__global__ void k_scan(){
    int* hist = blockIdx.x ? g_histd : g_hists;
    int* off  = blockIdx.x ? g_offd  : g_offs;
    int* cur  = blockIdx.x ? g_curd  : g_curs;
    __shared__ int wsum[32];
    int t = threadIdx.x;         // 1024
    int lane = t & 31, wid = t >> 5;
    int4 a = ((const int4*)hist)[2*t];
    int4 b = ((const int4*)hist)[2*t+1];
    int l0=a.x, l1=l0+a.y, l2=l1+a.z, l3=l2+a.w;
    int l4=l3+b.x, l5=l4+b.y, l6=l5+b.z, l7=l6+b.w;
    int4 z4 = make_int4(0,0,0,0);
    ((int4*)hist)[2*t]   = z4;
    ((int4*)hist)[2*t+1] = z4;
    int tot = l7;
    int pre = tot;
    #pragma unroll
    for (int o=1;o<32;o<<=1){ int v=__shfl_up_sync(0xffffffffu, pre, o); if (lane>=o) pre += v; }
    int wex = pre - tot;
    if (lane == 31) wsum[wid] = pre;
    __syncthreads();
    if (wid == 0){
        int v = wsum[lane];
        int p = v;
        #pragma unroll
        for (int o=1;o<32;o<<=1){ int u=__shfl_up_sync(0xffffffffu, p, o); if (lane>=o) p += u; }
        wsum[lane] = p - v;
    }
    __syncthreads();
    int base = wsum[wid] + wex;
    int4 o0 = make_int4(base,    base+l0, base+l1, base+l2);
    int4 o1 = make_int4(base+l3, base+l4, base+l5, base+l6);
    ((int4*)off)[2*t]   = o0;  ((int4*)off)[2*t+1] = o1;
    ((int4*)cur)[2*t]   = o0;  ((int4*)cur)[2*t+1] = o1;
    if (t == 1023) off[NN] = base + l7;
}

// ---------------- scatter: CSR build + w0 = 1/mult ----------------------------
__global__ void k_scatter(const int* __restrict__ src, const int* __restrict__ dst){
    int e2 = blockIdx.x*blockDim.x + threadIdx.x;
    if (e2 >= EE/2) return;
    int2 s = ((const int2*)src)[e2];
    int2 d = ((const int2*)dst)[e2];
    uchar2 b = ((const uchar2*)g_bits)[e2];
    int kx = (s.x<<13)|d.x, ky = (s.y<<13)|d.y;
    unsigned cx = (g_mult[kx>>2] >> ((kx&3)*8)) & 0xFFu;   // stable after histbits
    unsigned cy = (g_mult[ky>>2] >> ((ky&3)*8)) & 0xFFu;
    int bx = ((int)b.x) << 14;
    int by = ((int)b.y) << 14;
    int px = atomicAdd(&g_curs[s.x], 1);
    g_sent[px] = d.x | bx;  g_w0[px] = 1.f/(float)cx;
    g_dent[atomicAdd(&g_curd[d.x], 1)] = s.x | bx;
    int py = atomicAdd(&g_curs[s.y], 1);
    g_sent[py] = d.y | by;  g_w0[py] = 1.f/(float)cy;
    g_dent[atomicAdd(&g_curd[d.y], 1)] = s.y | by;
}

// ---------------- k1: AH gather + Z = AH@Ww.T+Wb + ft0 = Z@fc0 (16-lane grp) --
__global__ void k1(const float* __restrict__ h, const float* __restrict__ Ww,
                   const float* __restrict__ Wb, const float* __restrict__ fc0){
    __shared__ float sW[DD*DD];     // sW[k*64+j] = Ww[j][k]
    __shared__ float sF[DD*DD];     // fc0 natural [k][j]
    __shared__ float srow[16][DD];
    int t = threadIdx.x;            // 256
    for (int x=t; x<DD*DD; x+=256){
        int k = x >> 6, j = x & 63;
        sW[x] = Ww[j*DD + k];
        sF[x] = fc0[x];
    }
    __syncthreads();
    int g  = t >> 4;
    int hl = t & 15;
    unsigned gmask = 0xFFFFu << (t & 16);
    int row = blockIdx.x*16 + g;
    int lo = g_offs[row], hi = g_offs[row+1];
    float4 acc = make_float4(0,0,0,0);
    #pragma unroll 4
    for (int i=lo; i<hi; i++){
        int w = g_sent[i];
        float w0 = g_w0[i];
        float4 v = ((const float4*)(h + (size_t)(w & 0x3FFF)*DD))[hl];
        acc.x += w0*v.x; acc.y += w0*v.y; acc.z += w0*v.z; acc.w += w0*v.w;
    }
    ((float4*)&srow[g][0])[hl] = acc;
    __syncwarp(gmask);
    float4 z = ((const float4*)Wb)[hl];
    #pragma unroll 8
    for (int k=0;k<DD;k++){
        float a = srow[g][k];
        float4 wv = ((const float4*)(sW + k*DD))[hl];
        z.x += a*wv.x; z.y += a*wv.y; z.z += a*wv.z; z.w += a*wv.w;
    }
    ((float4*)(g_Z + (size_t)row*DD))[hl] = z;
    __syncwarp(gmask);
    ((float4*)&srow[g][0])[hl] = z;
    __syncwarp(gmask);
    float4 f = make_float4(0,0,0,0);
    #pragma unroll 8
    for (int k=0;k<DD;k++){
        float a = srow[g][k];
        float4 wv = ((const float4*)(sF + k*DD))[hl];
        f.x += a*wv.x; f.y += a*wv.y; f.z += a*wv.z; f.w += a*wv.w;
    }
    ((float4*)(g_ft0 + (size_t)row*DD))[hl] = f;
}

// ---------------- k2: AZ1/AZ2 gather + ft1/ft2 + motif out-flags --------------
__global__ void k2(const float* __restrict__ fc1, const float* __restrict__ fc2){
    __shared__ float sF1[DD*DD];
    __shared__ float sF2[DD*DD];
    __shared__ float srow[16][2*DD];
    int t = threadIdx.x;   // 256
    for (int x=t; x<DD*DD; x+=256){ sF1[x] = fc1[x]; sF2[x] = fc2[x]; }
    __syncthreads();
    int g  = t >> 4;
    int hl = t & 15;
    unsigned gmask = 0xFFFFu << (t & 16);
    int row = blockIdx.x*16 + g;
    int lo = g_offs[row], hi = g_offs[row+1];
    float4 acc1 = make_float4(0,0,0,0), acc2 = make_float4(0,0,0,0);
    int o1 = 0, o2 = 0;
    #pragma unroll 4
    for (int i=lo; i<hi; i++){
        int w = g_sent[i];
        float w0 = g_w0[i];
        float w1 = (w & (1<<14)) ? w0 : 0.f;
        float w2 = (w & (1<<15)) ? w0 : 0.f;
        o1 |= (w >> 14) & 1;
        o2 |= (w >> 15) & 1;
        float4 v = ((const float4*)(g_Z + (size_t)(w & 0x3FFF)*DD))[hl];
        acc1.x += w1*v.x; acc1.y += w1*v.y; acc1.z += w1*v.z; acc1.w += w1*v.w;
        acc2.x += w2*v.x; acc2.y += w2*v.y; acc2.z += w2*v.z; acc2.w += w2*v.w;
    }
    if (hl == 0){ g_nm1[row] = o1; g_nm2[row] = o2; }   // always written: self-cleaning
    ((float4*)&srow[g][0])[hl]  = acc1;
    ((float4*)&srow[g][DD])[hl] = acc2;
    __syncwarp(gmask);
    float4 f1 = make_float4(0,0,0,0), f2 = make_float4(0,0,0,0);
    #pragma unroll 8
    for (int k=0;k<DD;k++){
        float a1 = srow[g][k];
        float a2 = srow[g][DD+k];
        float4 w1 = ((const float4*)(sF1 + k*DD))[hl];
        float4 w2 = ((const float4*)(sF2 + k*DD))[hl];
        f1.x += a1*w1.x; f1.y += a1*w1.y; f1.z += a1*w1.z; f1.w += a1*w1.w;
        f2.x += a2*w2.x; f2.y += a2*w2.y; f2.z += a2*w2.z; f2.w += a2*w2.w;
    }
    ((float4*)(g_ft1 + (size_t)row*DD))[hl] = f1;
    ((float4*)(g_ft2 + (size_t)row*DD))[hl] = f2;
}

// ---------------- fused attention + in-flags + table cleanup ------------------
#define ONLINE_UPD4(m, den, acc, p, v) do {              \
    float _mn = fmaxf((m), (p));                         \
    float _sc = __expf((m) - _mn);                       \
    float _w  = __expf((p) - _mn);                       \
    (den) = (den)*_sc + _w;                              \
    (acc).x = (acc).x*_sc + _w*(v).x;                    \
    (acc).y = (acc).y*_sc + _w*(v).y;                    \
    (acc).z = (acc).z*_sc + _w*(v).z;                    \
    (acc).w = (acc).w*_sc + _w*(v).w;                    \
    (m) = _mn;                                           \
} while(0)

#define ONLINE_UPD4X2(m, den, acc, pa, va, pb, vb) do {  \
    float _mn = fmaxf((m), fmaxf((pa), (pb)));           \
    float _sc = __expf((m) - _mn);                       \
    float _wa = __expf((pa) - _mn);                      \
    float _wb = __expf((pb) - _mn);                      \
    (den) = (den)*_sc + _wa + _wb;                       \
    (acc).x = (acc).x*_sc + _wa*(va).x + _wb*(vb).x;     \
    (acc).y = (acc).y*_sc + _wa*(va).y + _wb*(vb).y;     \
    (acc).z = (acc).z*_sc + _wa*(va).z + _wb*(vb).z;     \
    (acc).w = (acc).w*_sc + _wa*(va).w + _wb*(vb).w;     \
    (m) = _mn;                                           \
} while(0)

__device__ __forceinline__ float red16(float p, unsigned gmask){
    #pragma unroll
    for (int o=8;o;o>>=1) p += __shfl_xor_sync(gmask, p, o);
    return p;
}
__device__ __forceinline__ float dot4(float4 a, float4 b){
    return a.x*b.x + a.y*b.y + a.z*b.z + a.w*b.w;
}

__global__ void k_attn(){
    __shared__ float sacc[3*DD];
    int t = threadIdx.x;
    for (int j=t; j<3*DD; j+=256) sacc[j] = 0.f;
    __syncthreads();
    int hl = t & 15;
    unsigned gmask = 0xFFFFu << (t & 16);
    int d  = (blockIdx.x*256 + t) >> 4;       // one dst row per 16-group
    if (d < NN){
        int lo = g_offd[d], hi = g_offd[d+1];
        if (lo < hi){
            float4 f0 = ((const float4*)(g_ft0 + (size_t)d*DD))[hl];
            float4 f1 = ((const float4*)(g_ft1 + (size_t)d*DD))[hl];
            float4 f2 = ((const float4*)(g_ft2 + (size_t)d*DD))[hl];
            float m0=-FLT_MAX, den0=0.f; float4 a0 = make_float4(0,0,0,0);
            float m1=-FLT_MAX, den1=0.f; float4 a1 = make_float4(0,0,0,0);
            float m2=-FLT_MAX, den2=0.f; float4 a2 = make_float4(0,0,0,0);
            int i = lo;
            for (; i+1 < hi; i += 2){
                int wa = g_dent[i];
                int wb = g_dent[i+1];
                int sa = wa & 0x3FFF, sb = wb & 0x3FFF;
                if (hl == 0){                              // clean mult table
                    g_mult[((sa<<13)|d)>>2] = 0;
                    g_mult[((sb<<13)|d)>>2] = 0;
                }
                float4 va = ((const float4*)(g_ft0 + (size_t)sa*DD))[hl];
                float4 vb = ((const float4*)(g_ft0 + (size_t)sb*DD))[hl];
                float pa = red16(dot4(va, f0), gmask) * 0.125f;
                float pb = red16(dot4(vb, f0), gmask) * 0.125f;
                ONLINE_UPD4X2(m0, den0, a0, pa, va, pb, vb);
                if (wa & (1<<14)){
                    float4 v1 = ((const float4*)(g_ft1 + (size_t)sa*DD))[hl];
                    float p1 = red16(dot4(v1, f1), gmask) * 0.125f;
                    ONLINE_UPD4(m1, den1, a1, p1, v1);
                }
                if (wb & (1<<14)){
                    float4 v1 = ((const float4*)(g_ft1 + (size_t)sb*DD))[hl];
                    float p1 = red16(dot4(v1, f1), gmask) * 0.125f;
                    ONLINE_UPD4(m1, den1, a1, p1, v1);
                }
                if (wa & (1<<15)){
                    float4 v2 = ((const float4*)(g_ft2 + (size_t)sa*DD))[hl];
                    float p2 = red16(dot4(v2, f2), gmask) * 0.125f;
                    ONLINE_UPD4(m2, den2, a2, p2, v2);
                }
                if (wb & (1<<15)){
                    float4 v2 = ((const float4*)(g_ft2 + (size_t)sb*DD))[hl];
                    float p2 = red16(dot4(v2, f2), gmask) * 0.125f;
                    ONLINE_UPD4(m2, den2, a2, p2, v2);
                }
            }
            if (i < hi){
                int w = g_dent[i];
                int s = w & 0x3FFF;
                if (hl == 0) g_mult[((s<<13)|d)>>2] = 0;
                float4 v0 = ((const float4*)(g_ft0 + (size_t)s*DD))[hl];
                float p0 = red16(dot4(v0, f0), gmask) * 0.125f;
                ONLINE_UPD4(m0, den0, a0, p0, v0);
                if (w & (1<<14)){
                    float4 v1 = ((const float4*)(g_ft1 + (size_t)s*DD))[hl];
                    float p1 = red16(dot4(v1, f1), gmask) * 0.125f;
                    ONLINE_UPD4(m1, den1, a1, p1, v1);
                }
                if (w & (1<<15)){
                    float4 v2 = ((const float4*)(g_ft2 + (size_t)s*DD))[hl];
                    float p2 = red16(dot4(v2, f2), gmask) * 0.125f;
                    ONLINE_UPD4(m2, den2, a2, p2, v2);
                }
            }
            if (hl == 0){                                  // in-flags (dst side)
                if (den1 > 0.f) g_nm1[d] = 1;
                if (den2 > 0.f) g_nm2[d] = 1;
            }
            float r0 = 1.f/fmaxf(den0, 1e-9f);
            atomicAdd(&sacc[4*hl+0], a0.x*r0); atomicAdd(&sacc[4*hl+1], a0.y*r0);
            atomicAdd(&sacc[4*hl+2], a0.z*r0); atomicAdd(&sacc[4*hl+3], a0.w*r0);
            if (den1 > 0.f){
                float r1 = 1.f/den1;
                atomicAdd(&sacc[DD+4*hl+0], a1.x*r1); atomicAdd(&sacc[DD+4*hl+1], a1.y*r1);
                atomicAdd(&sacc[DD+4*hl+2], a1.z*r1); atomicAdd(&sacc[DD+4*hl+3], a1.w*r1);
            }
            if (den2 > 0.f){
                float r2 = 1.f/den2;
                atomicAdd(&sacc[2*DD+4*hl+0], a2.x*r2); atomicAdd(&sacc[2*DD+4*hl+1], a2.y*r2);
                atomicAdd(&sacc[2*DD+4*hl+2], a2.z*r2); atomicAdd(&sacc[2*DD+4*hl+3], a2.w*r2);
            }
        }
    }
    __syncthreads();
    for (int j=t; j<3*DD; j+=256) atomicAdd(&g_pool[j], sacc[j]);
}

// ---------------- counts + final linear + pool clean ---------------------------
__global__ void k_nfinal(const float* __restrict__ lw, const float* __restrict__ lb,
                         float* __restrict__ out){
    __shared__ int sc1, sc2;
    __shared__ float s0[3*DD], s1[3*DD];
    int t = threadIdx.x;   // 256
    if (t == 0){ sc1 = 0; sc2 = 0; }
    __syncthreads();
    int c1 = 0, c2 = 0;
    for (int i=t; i<NN; i+=256){ c1 += g_nm1[i]; c2 += g_nm2[i]; }
    #pragma unroll
    for (int o=16;o;o>>=1){
        c1 += __shfl_xor_sync(0xffffffffu, c1, o);
        c2 += __shfl_xor_sync(0xffffffffu, c2, o);
    }
    if ((t & 31) == 0){ atomicAdd(&sc1, c1); atomicAdd(&sc2, c2); }
    __syncthreads();
    if (t < 3*DD){
        int k = t >> 6;
        float cnt = (k==0) ? (float)NN : fmaxf((float)(k==1 ? sc1 : sc2), 1.f);
        float p = g_pool[t] / cnt;
        g_pool[t] = 0.f;
        s0[t] = p * lw[t*2 + 0];
        s1[t] = p * lw[t*2 + 1];
    }
    __syncthreads();
    if (t == 0){
        float a = 0.f, b = 0.f;
        for (int i=0;i<3*DD;i++){ a += s0[i]; b += s1[i]; }
        out[0] = a + lb[0];
        out[1] = b + lb[1];
    }
}

// ---------------- host launcher -----------------------------------------------
extern "C" void kernel_launch(void* const* d_in, const int* in_sizes, int n_in,
                              void* d_out, int out_size){
    const float* h    = (const float*)d_in[0];
    const float* A1   = (const float*)d_in[2];
    const float* A2   = (const float*)d_in[3];
    const float* Ww   = (const float*)d_in[4];
    const float* Wb   = (const float*)d_in[5];
    const float* fc0  = (const float*)d_in[6];
    const float* fc1  = (const float*)d_in[7];
    const float* fc2  = (const float*)d_in[8];
    const float* linw = (const float*)d_in[9];
    const float* linb = (const float*)d_in[10];
    const int*   src  = (const int*)d_in[11];
    const int*   dst  = (const int*)d_in[12];
    float* out = (float*)d_out;

    k_histbits<<<512,  256>>>(src, dst, A1, A2);
    k_scan    <<<2,   1024>>>();
    k_scatter <<<1024, 256>>>(src, dst);
    k1        <<<512,  256>>>(h, Ww, Wb, fc0);
    k2        <<<512,  256>>>(fc1, fc2);
    k_attn    <<<512,  256>>>();
    k_nfinal  <<<1,    256>>>(linw, linb, out);
    (void)in_sizes; (void)n_in; (void)out_size;
}